// round 13
// baseline (speedup 1.0000x reference)
#include <cuda_runtime.h>
#include <cstdint>
#include <math.h>

#define S_LEN 3072
#define HID 3584
#define NH 16
#define NKV 8
#define HD 256
#define WIN 2048
#define QKV_N 8192
#define NEGF -2.3819763e38f
#define QSCALE 0.0625f
#define AO_N 4096
#define VOFF (NH * HD + NKV * HD)

typedef unsigned long long u64;

// ---------------- bf16 split helpers ----------------
__device__ __forceinline__ float hif(float a) {
    return __uint_as_float(__float_as_uint(a) & 0xFFFF0000u);
}
__device__ __forceinline__ uint32_t hipair(float a, float b) {
    uint32_t r;
    asm("prmt.b32 %0, %1, %2, 0x7632;"
        : "=r"(r) : "r"(__float_as_uint(a)), "r"(__float_as_uint(b)));
    return r;
}
__device__ __forceinline__ uint32_t lopair(float a, float b) {
    uint32_t r;
    asm("cvt.rn.bf16x2.f32 %0, %1, %2;"
        : "=r"(r) : "f"(b - hif(b)), "f"(a - hif(a)));
    return r;
}
__device__ __forceinline__ uint16_t hi16(float a) {
    return (uint16_t)(__float_as_uint(a) >> 16);
}
__device__ __forceinline__ uint16_t lo16(float a) {
    uint16_t u;
    asm("cvt.rn.bf16.f32 %0, %1;" : "=h"(u) : "f"(a - hif(a)));
    return u;
}

__device__ __forceinline__ void mma_bf16(float* c, uint32_t a0, uint32_t a1,
                                         uint32_t a2, uint32_t a3,
                                         uint32_t b0, uint32_t b1) {
    asm volatile(
        "mma.sync.aligned.m16n8k16.row.col.f32.bf16.bf16.f32 "
        "{%0,%1,%2,%3}, {%4,%5,%6,%7}, {%8,%9}, {%0,%1,%2,%3};"
        : "+f"(c[0]), "+f"(c[1]), "+f"(c[2]), "+f"(c[3])
        : "r"(a0), "r"(a1), "r"(a2), "r"(a3), "r"(b0), "r"(b1));
}

// ---------------- scratch ----------------
__device__ float g_qkv[S_LEN * QKV_N];
__device__ float g_hidT[S_LEN * HID];
__device__ float g_qwT[QKV_N * HID];
__device__ uint16_t g_kh[NKV * S_LEN * HD];
__device__ uint16_t g_kl[NKV * S_LEN * HD];
__device__ uint16_t g_vh[NKV * HD * S_LEN];
__device__ uint16_t g_vl[NKV * HD * S_LEN];
__device__ uint16_t g_ah[S_LEN * AO_N];
__device__ uint16_t g_al[S_LEN * AO_N];
__device__ uint16_t g_wh[HID * AO_N];
__device__ uint16_t g_wl[HID * AO_N];

// ---------------- common asm helpers ----------------
__device__ __forceinline__ uint32_t cvta_sh(const void* p) {
    uint32_t a;
    asm("{ .reg .u64 t; cvta.to.shared.u64 t, %1; cvt.u32.u64 %0, t; }"
        : "=r"(a) : "l"(p));
    return a;
}
__device__ __forceinline__ void cp16(uint32_t dst, const void* src) {
    asm volatile("cp.async.cg.shared.global [%0], [%1], 16;"
                 :: "r"(dst), "l"(src));
}
__device__ __forceinline__ void cp_commit() {
    asm volatile("cp.async.commit_group;" ::: "memory");
}
__device__ __forceinline__ void cp_wait1() {
    asm volatile("cp.async.wait_group 1;" ::: "memory");
}
__device__ __forceinline__ void cp_wait0() {
    asm volatile("cp.async.wait_group 0;" ::: "memory");
}
__device__ __forceinline__ uint32_t f2tf32(float x) {
    uint32_t r;
    asm("cvt.rna.tf32.f32 %0, %1;" : "=r"(r) : "f"(x));
    return r;
}
__device__ __forceinline__ void mma_tf32(float* c, const uint32_t* a,
                                         const uint32_t* b) {
    asm volatile(
        "mma.sync.aligned.m16n8k8.row.col.f32.tf32.tf32.f32 "
        "{%0,%1,%2,%3}, {%4,%5,%6,%7}, {%8,%9}, {%0,%1,%2,%3};"
        : "+f"(c[0]), "+f"(c[1]), "+f"(c[2]), "+f"(c[3])
        : "r"(a[0]), "r"(a[1]), "r"(a[2]), "r"(a[3]), "r"(b[0]), "r"(b[1]));
}

// =====================================================================
// pre-round fp32 -> tf32 with column permutation:
// within each 8-col group, output order is [0,4,1,5,2,6,3,7], so the
// tf32 mma fragment pairs (c, c+4) become ADJACENT in memory -> LDS.64.
// =====================================================================
__global__ void __launch_bounds__(256) cvt_tf32_perm(const float* __restrict__ src,
                                                     float* __restrict__ dst, int n8) {
    for (int i = blockIdx.x * blockDim.x + threadIdx.x; i < n8;
         i += gridDim.x * blockDim.x) {
        const float4 x = ((const float4*)src)[2 * i];
        const float4 y = ((const float4*)src)[2 * i + 1];
        float4 o0, o1;
        o0.x = __uint_as_float(f2tf32(x.x));
        o0.y = __uint_as_float(f2tf32(y.x));
        o0.z = __uint_as_float(f2tf32(x.y));
        o0.w = __uint_as_float(f2tf32(y.y));
        o1.x = __uint_as_float(f2tf32(x.z));
        o1.y = __uint_as_float(f2tf32(y.z));
        o1.z = __uint_as_float(f2tf32(x.w));
        o1.w = __uint_as_float(f2tf32(y.w));
        ((float4*)dst)[2 * i]     = o0;
        ((float4*)dst)[2 * i + 1] = o1;
    }
}

// =====================================================================
// tf32 mma.sync GEMM for QKV projection — 2 CTAs/SM, LDS.64 fragment loads
// (operands stored column-permuted by cvt_tf32_perm)
// =====================================================================
#define GSTAGE 3
#define SROW 36
#define STAGE_FLOATS (128 * SROW)
#define STAGE_BYTES  (STAGE_FLOATS * 4 * 2)
#define GEMM_SMEM (GSTAGE * STAGE_BYTES)

__device__ __forceinline__ void g_load_stage(uint32_t smem_base,
                                             const float* __restrict__ A,
                                             const float* __restrict__ B,
                                             int K, int m0, int n0,
                                             int stage, int chunk, int tid) {
    const uint32_t sa = smem_base + stage * STAGE_BYTES;
    const uint32_t sb = sa + STAGE_FLOATS * 4;
    const float* Ab = A + (size_t)m0 * K + chunk * 32;
    const float* Bb = B + (size_t)n0 * K + chunk * 32;
#pragma unroll
    for (int i = 0; i < 4; i++) {
        const int u = tid + i * 256;
        const int r = u >> 3, ch = u & 7;
        const uint32_t off = (uint32_t)r * (SROW * 4) + ch * 16;
        cp16(sa + off, Ab + (size_t)r * K + ch * 4);
        cp16(sb + off, Bb + (size_t)r * K + ch * 4);
    }
    cp_commit();
}

__global__ void __launch_bounds__(256, 2) gemm_mma(const float* __restrict__ A,
                                                   const float* __restrict__ B,
                                                   float* __restrict__ C,
                                                   int M, int N, int K) {
    extern __shared__ __align__(16) char dynsm[];
    const int tid = threadIdx.x;
    const int wid = tid >> 5, lane = tid & 31;
    const int warp_m = wid & 1, warp_n = wid >> 1;
    const int m0 = blockIdx.x * 128, n0 = blockIdx.y * 128;
    const uint32_t smem_base = cvta_sh(dynsm);

    const int lr = lane >> 2;
    const int lc = lane & 3;

    float acc[4][4][4];
#pragma unroll
    for (int mi = 0; mi < 4; mi++)
#pragma unroll
        for (int ni = 0; ni < 4; ni++)
#pragma unroll
            for (int r = 0; r < 4; r++) acc[mi][ni][r] = 0.f;

    const int nk = K >> 5;

    g_load_stage(smem_base, A, B, K, m0, n0, 0, 0, tid);
    g_load_stage(smem_base, A, B, K, m0, n0, 1, 1, tid);

    for (int k0 = 0; k0 < nk; k0++) {
        cp_wait1();
        __syncthreads();
        if (k0 + 2 < nk)
            g_load_stage(smem_base, A, B, K, m0, n0, (k0 + 2) % GSTAGE,
                         k0 + 2, tid);

        const uint32_t* sA = (const uint32_t*)(dynsm + (size_t)(k0 % GSTAGE) * STAGE_BYTES);
        const uint32_t* sB = sA + STAGE_FLOATS;

#pragma unroll
        for (int ks = 0; ks < 4; ks++) {
            const int c2 = ks * 8 + 2 * lc;   // permuted pair base
            uint32_t af[4][4], bf[4][2];
#pragma unroll
            for (int mi = 0; mi < 4; mi++) {
                const int r = warp_m * 64 + mi * 16 + lr;
                const uint2 a02 = *(const uint2*)&sA[r * SROW + c2];
                const uint2 a13 = *(const uint2*)&sA[(r + 8) * SROW + c2];
                af[mi][0] = a02.x;
                af[mi][1] = a13.x;
                af[mi][2] = a02.y;
                af[mi][3] = a13.y;
            }
#pragma unroll
            for (int ni = 0; ni < 4; ni++) {
                const int n = warp_n * 32 + ni * 8 + lr;
                const uint2 b01 = *(const uint2*)&sB[n * SROW + c2];
                bf[ni][0] = b01.x;
                bf[ni][1] = b01.y;
            }
#pragma unroll
            for (int mi = 0; mi < 4; mi++)
#pragma unroll
                for (int ni = 0; ni < 4; ni++)
                    mma_tf32(acc[mi][ni], af[mi], bf[ni]);
        }
    }

#pragma unroll
    for (int mi = 0; mi < 4; mi++) {
        const int row0 = m0 + warp_m * 64 + mi * 16 + lr;
#pragma unroll
        for (int ni = 0; ni < 4; ni++) {
            const int col = n0 + warp_n * 32 + ni * 8 + 2 * lc;
            float* p0 = C + (size_t)row0 * N + col;
            float* p1 = p0 + 8 * N;
            *(float2*)p0 = make_float2(acc[mi][ni][0], acc[mi][ni][1]);
            *(float2*)p1 = make_float2(acc[mi][ni][2], acc[mi][ni][3]);
        }
    }
}

// =====================================================================
// split fp32 -> bf16 hi/lo planes (o_w only)
// =====================================================================
__global__ void __launch_bounds__(256) split_planes(const float* __restrict__ src,
                                                    uint16_t* __restrict__ hi,
                                                    uint16_t* __restrict__ lo,
                                                    int n4) {
    for (int i = blockIdx.x * blockDim.x + threadIdx.x; i < n4;
         i += gridDim.x * blockDim.x) {
        const float4 v = ((const float4*)src)[i];
        ushort4 h, l;
        h.x = hi16(v.x); h.y = hi16(v.y); h.z = hi16(v.z); h.w = hi16(v.w);
        l.x = lo16(v.x); l.y = lo16(v.y); l.z = lo16(v.z); l.w = lo16(v.w);
        ((ushort4*)hi)[i] = h;
        ((ushort4*)lo)[i] = l;
    }
}

// =====================================================================
// bf16x3 split GEMM for O-projection — 2-stage double buffer, 2 CTAs/SM
// =====================================================================
#define OSTAGE 2
#define BSTR 20
#define PLANE_W (128 * BSTR)
#define OSTG_BYTES (4 * PLANE_W * 4)
#define OGEMM_SMEM (OSTAGE * OSTG_BYTES)

__device__ __forceinline__ void o_load_stage(uint32_t smem_base,
                                             const uint16_t* __restrict__ Ah,
                                             const uint16_t* __restrict__ Al,
                                             const uint16_t* __restrict__ Bh,
                                             const uint16_t* __restrict__ Bl,
                                             int K, int m0, int n0,
                                             int stage, int chunk, int tid) {
    const uint32_t s0 = smem_base + stage * OSTG_BYTES;
    const uint16_t* p0 = Ah + (size_t)m0 * K + chunk * 32;
    const uint16_t* p1 = Al + (size_t)m0 * K + chunk * 32;
    const uint16_t* p2 = Bh + (size_t)n0 * K + chunk * 32;
    const uint16_t* p3 = Bl + (size_t)n0 * K + chunk * 32;
#pragma unroll
    for (int i = 0; i < 2; i++) {
        const int u = tid + i * 256;
        const int r = u >> 2, ch = u & 3;
        const uint32_t off = (uint32_t)r * (BSTR * 4) + ch * 16;
        const size_t go = (size_t)r * K + ch * 8;
        cp16(s0 + 0 * PLANE_W * 4 + off, p0 + go);
        cp16(s0 + 1 * PLANE_W * 4 + off, p1 + go);
        cp16(s0 + 2 * PLANE_W * 4 + off, p2 + go);
        cp16(s0 + 3 * PLANE_W * 4 + off, p3 + go);
    }
    cp_commit();
}

__global__ void __launch_bounds__(256, 2) gemm_bf3(const uint16_t* __restrict__ Ah,
                                                   const uint16_t* __restrict__ Al,
                                                   const uint16_t* __restrict__ Bh,
                                                   const uint16_t* __restrict__ Bl,
                                                   float* __restrict__ C,
                                                   int M, int N, int K) {
    extern __shared__ __align__(16) char dynsm[];
    const int tid = threadIdx.x;
    const int wid = tid >> 5, lane = tid & 31;
    const int warp_m = wid & 1, warp_n = wid >> 1;
    const int m0 = blockIdx.x * 128, n0 = blockIdx.y * 128;
    const uint32_t smem_base = cvta_sh(dynsm);

    const int lr = lane >> 2, lq = lane & 3;

    float acc[4][4][4];
#pragma unroll
    for (int mi = 0; mi < 4; mi++)
#pragma unroll
        for (int ni = 0; ni < 4; ni++)
#pragma unroll
            for (int r = 0; r < 4; r++) acc[mi][ni][r] = 0.f;

    const int nk = K >> 5;

    o_load_stage(smem_base, Ah, Al, Bh, Bl, K, m0, n0, 0, 0, tid);

    for (int k0 = 0; k0 < nk; k0++) {
        if (k0 + 1 < nk) {
            o_load_stage(smem_base, Ah, Al, Bh, Bl, K, m0, n0,
                         (k0 + 1) & 1, k0 + 1, tid);
            cp_wait1();
        } else {
            cp_wait0();
        }
        __syncthreads();

        const uint32_t* sAh = (const uint32_t*)(dynsm + (size_t)(k0 & 1) * OSTG_BYTES);
        const uint32_t* sAl = sAh + PLANE_W;
        const uint32_t* sBh = sAh + 2 * PLANE_W;
        const uint32_t* sBl = sAh + 3 * PLANE_W;

#pragma unroll
        for (int ks = 0; ks < 2; ks++) {
            uint32_t ah[4][4], al[4][4], bh[4][2], bl[4][2];
#pragma unroll
            for (int mi = 0; mi < 4; mi++) {
                const int r = warp_m * 64 + mi * 16 + lr;
                const int o = r * BSTR + ks * 8 + lq;
                ah[mi][0] = sAh[o];
                ah[mi][1] = sAh[o + 8 * BSTR];
                ah[mi][2] = sAh[o + 4];
                ah[mi][3] = sAh[o + 8 * BSTR + 4];
                al[mi][0] = sAl[o];
                al[mi][1] = sAl[o + 8 * BSTR];
                al[mi][2] = sAl[o + 4];
                al[mi][3] = sAl[o + 8 * BSTR + 4];
            }
#pragma unroll
            for (int ni = 0; ni < 4; ni++) {
                const int n = warp_n * 32 + ni * 8 + lr;
                const int o = n * BSTR + ks * 8 + lq;
                bh[ni][0] = sBh[o];
                bh[ni][1] = sBh[o + 4];
                bl[ni][0] = sBl[o];
                bl[ni][1] = sBl[o + 4];
            }
#pragma unroll
            for (int mi = 0; mi < 4; mi++)
#pragma unroll
                for (int ni = 0; ni < 4; ni++) {
                    mma_bf16(acc[mi][ni], ah[mi][0], ah[mi][1], ah[mi][2], ah[mi][3],
                             bh[ni][0], bh[ni][1]);
                    mma_bf16(acc[mi][ni], ah[mi][0], ah[mi][1], ah[mi][2], ah[mi][3],
                             bl[ni][0], bl[ni][1]);
                    mma_bf16(acc[mi][ni], al[mi][0], al[mi][1], al[mi][2], al[mi][3],
                             bh[ni][0], bh[ni][1]);
                }
        }
        __syncthreads();
    }

#pragma unroll
    for (int mi = 0; mi < 4; mi++) {
        const int row0 = m0 + warp_m * 64 + mi * 16 + lr;
#pragma unroll
        for (int ni = 0; ni < 4; ni++) {
            const int col = n0 + warp_n * 32 + ni * 8 + 2 * lq;
            float* p0 = C + (size_t)row0 * N + col;
            float* p1 = p0 + 8 * N;
            *(float2*)p0 = make_float2(acc[mi][ni][0], acc[mi][ni][1]);
            *(float2*)p1 = make_float2(acc[mi][ni][2], acc[mi][ni][3]);
        }
    }
}

// ---------------------------------------------------------------------------
// RoPE: q in-place (fp32, scaled), k -> bf16 hi/lo planes [NKV][S][HD]
// ---------------------------------------------------------------------------
__global__ void __launch_bounds__(256) rope_scatter(const float* __restrict__ freqs,
                                                    const int* __restrict__ widx) {
    const int l = blockIdx.x;
    const int t = threadIdx.x;
    const int dst = widx[l];
    const float* fr = freqs + (size_t)l * HD;
    float* row = g_qkv + (size_t)l * QKV_N;

    for (int p = t; p < NH * 128; p += 256) {
        const int hh = p >> 7, d = p & 127;
        const float c = fr[2 * d], s = fr[2 * d + 1];
        float* q = row + hh * HD;
        const float x1 = q[d], x2 = q[d + 128];
        q[d]       = (x1 * c - x2 * s) * QSCALE;
        q[d + 128] = (x1 * s + x2 * c) * QSCALE;
    }
    for (int p = t; p < NKV * 128; p += 256) {
        const int hh = p >> 7, d = p & 127;
        const float c = fr[2 * d], s = fr[2 * d + 1];
        const float* kk = row + NH * HD + hh * HD;
        const float x1 = kk[d], x2 = kk[d + 128];
        const float y1 = x1 * c - x2 * s;
        const float y2 = x1 * s + x2 * c;
        const size_t base = ((size_t)hh * S_LEN + dst) * HD;
        g_kh[base + d]       = hi16(y1);
        g_kh[base + d + 128] = hi16(y2);
        g_kl[base + d]       = lo16(y1);
        g_kl[base + d + 128] = lo16(y2);
    }
}

// ---------------------------------------------------------------------------
// V transpose + split
// ---------------------------------------------------------------------------
__global__ void __launch_bounds__(256) transpose_split_v() {
    __shared__ float sm[64][65];
    const int j0 = blockIdx.x * 64, d0 = blockIdx.y * 64, kvh = blockIdx.z;
    const int t = threadIdx.x;
#pragma unroll
    for (int i = 0; i < 16; i++) {
        const int idx = t + i * 256;
        const int jr = idx >> 6, dc = idx & 63;
        sm[jr][dc] = g_qkv[(size_t)(j0 + jr) * QKV_N + VOFF + kvh * HD + d0 + dc];
    }
    __syncthreads();
#pragma unroll
    for (int i = 0; i < 8; i++) {
        const int idx = t + i * 256;
        const int dr = idx >> 5, jp = idx & 31;
        const float f0 = sm[jp * 2][dr];
        const float f1 = sm[jp * 2 + 1][dr];
        const size_t go = ((size_t)kvh * HD + d0 + dr) * S_LEN + j0 + jp * 2;
        ushort2 h, l;
        h.x = hi16(f0); h.y = hi16(f1);
        l.x = lo16(f0); l.y = lo16(f1);
        *(ushort2*)(g_vh + go) = h;
        *(ushort2*)(g_vl + go) = l;
    }
}

// =====================================================================
// Flash attention (R11 config): 256 threads, heavy-first ordering.
// =====================================================================
#define QSTR 132
#define KROW 132
#define VSTR 36
#define PSTR 36
#define N_Q (64 * QSTR)
#define N_K (64 * KROW)
#define N_V (256 * VSTR)
#define N_P (64 * PSTR)
#define ATTN_SMEM ((2 * N_Q + 2 * N_K + 2 * N_V + 2 * N_P + 512) * 4)

__global__ void __launch_bounds__(256, 1) attn_mma() {
    extern __shared__ __align__(16) char smraw[];
    uint32_t* qh32 = (uint32_t*)smraw;
    uint32_t* ql32 = qh32 + N_Q;
    uint32_t* k0s  = ql32 + N_Q;
    uint32_t* k1s  = k0s + N_K;
    uint32_t* v0s  = k1s + N_K;
    uint32_t* v1s  = v0s + N_V;
    uint32_t* ph32 = v1s + N_V;
    uint32_t* pl32 = ph32 + N_P;
    float* partmx = (float*)(pl32 + N_P);
    float* partsm = partmx + 256;

    const uint32_t smem_base = cvta_sh(smraw);
    const uint32_t kb0 = smem_base + (2 * N_Q) * 4;
    const uint32_t kb1 = kb0 + N_K * 4;
    const uint32_t vb0 = kb1 + N_K * 4;
    const uint32_t vb1 = vb0 + N_V * 4;

    const int tid = threadIdx.x;
    const int lane = tid & 31, wid = tid >> 5;
    const int warp_m = wid & 1, warp_n = wid >> 1;
    const int lr = lane >> 2, lq = lane & 3;
    const int h = blockIdx.y, kvh = h >> 1;
    const int bx = gridDim.x - 1 - blockIdx.x;
    const int m0 = bx * 64;

    {
        const int row = tid >> 2, cb = (tid & 3) * 64;
        const float* q = g_qkv + (size_t)(m0 + row) * QKV_N + h * HD + cb;
#pragma unroll
        for (int i = 0; i < 16; i++) {
            const float4 v = *(const float4*)(q + i * 4);
            const int cp = (cb + i * 4) >> 1;
            qh32[row * QSTR + cp]     = hipair(v.x, v.y);
            qh32[row * QSTR + cp + 1] = hipair(v.z, v.w);
            ql32[row * QSTR + cp]     = lopair(v.x, v.y);
            ql32[row * QSTR + cp + 1] = lopair(v.z, v.w);
        }
    }

    float M_[2][2], L_[2][2], pcorr[2][2];
#pragma unroll
    for (int a = 0; a < 2; a++)
#pragma unroll
        for (int b = 0; b < 2; b++) { M_[a][b] = NEGF; L_[a][b] = 0.f; }

    float oacc[2][8][4];
#pragma unroll
    for (int mf = 0; mf < 2; mf++)
#pragma unroll
        for (int nf = 0; nf < 8; nf++)
#pragma unroll
            for (int c = 0; c < 4; c++) oacc[mf][nf][c] = 0.f;

    int lo = m0 - (WIN - 1);
    if (lo < 0) lo = 0;
    const int jt0 = lo >> 6, jt1 = bx;

    {
        const int j0 = jt0 * 64;
#pragma unroll
        for (int i = 0; i < 8; i++) {
            const int u = tid + i * 256;
            const int r = u >> 5, ch = u & 31;
            const size_t go = ((size_t)kvh * S_LEN + j0 + r) * HD + ch * 8;
            const uint32_t off = (uint32_t)r * (KROW * 4) + ch * 16;
            cp16(kb0 + off, g_kh + go);
            cp16(kb1 + off, g_kl + go);
        }
        cp_commit();
    }

    for (int jt = jt0; jt <= jt1; jt++) {
        const int j0 = jt * 64;
        const bool haveNext = (jt < jt1);

#pragma unroll
        for (int i = 0; i < 8; i++) {
            const int u = tid + i * 256;
            const int r = u >> 3, ch = u & 7;
            const size_t go = ((size_t)kvh * HD + r) * S_LEN + j0 + ch * 8;
            const uint32_t off = (uint32_t)r * (VSTR * 4) + ch * 16;
            cp16(vb0 + off, g_vh + go);
            cp16(vb1 + off, g_vl + go);
        }
        cp_commit();

        cp_wait1();
        __syncthreads();

        float sacc[2][2][4];
#pragma unroll
        for (int mf = 0; mf < 2; mf++)
#pragma unroll
            for (int nf = 0; nf < 2; nf++)
#pragma unroll
                for (int c = 0; c < 4; c++) sacc[mf][nf][c] = 0.f;

#pragma unroll
        for (int ks = 0; ks < 16; ks++) {
            uint32_t ah[2][4], al[2][4];
#pragma unroll
            for (int mf = 0; mf < 2; mf++) {
                const int r = warp_m * 32 + mf * 16 + lr;
                const int o = r * QSTR + ks * 8 + lq;
                ah[mf][0] = qh32[o];
                ah[mf][1] = qh32[o + 8 * QSTR];
                ah[mf][2] = qh32[o + 4];
                ah[mf][3] = qh32[o + 8 * QSTR + 4];
                al[mf][0] = ql32[o];
                al[mf][1] = ql32[o + 8 * QSTR];
                al[mf][2] = ql32[o + 4];
                al[mf][3] = ql32[o + 8 * QSTR + 4];
            }
#pragma unroll
            for (int nf = 0; nf < 2; nf++) {
                const int n = warp_n * 16 + nf * 8 + lr;
                const int o = n * KROW + ks * 8 + lq;
                const uint32_t bh0 = k0s[o], bh1 = k0s[o + 4];
                const uint32_t bl0 = k1s[o], bl1 = k1s[o + 4];
#pragma unroll
                for (int mf = 0; mf < 2; mf++) {
                    mma_bf16(sacc[mf][nf], ah[mf][0], ah[mf][1], ah[mf][2], ah[mf][3], bh0, bh1);
                    mma_bf16(sacc[mf][nf], ah[mf][0], ah[mf][1], ah[mf][2], ah[mf][3], bl0, bl1);
                    mma_bf16(sacc[mf][nf], al[mf][0], al[mf][1], al[mf][2], al[mf][3], bh0, bh1);
                }
            }
        }

#pragma unroll
        for (int mf = 0; mf < 2; mf++) {
            const int rl0 = warp_m * 32 + mf * 16 + lr;
            float mx0 = NEGF, mx1 = NEGF;
#pragma unroll
            for (int nf = 0; nf < 2; nf++) {
#pragma unroll
                for (int c = 0; c < 4; c++) {
                    const float s = sacc[mf][nf][c];
                    const float e = __expf(s * 0.04f);
                    float val = 50.f - 100.f / (e + 1.f);
                    const int gj = j0 + warp_n * 16 + nf * 8 + lq * 2 + (c & 1);
                    const int gi = m0 + rl0 + ((c & 2) ? 8 : 0);
                    if (gj > gi || gj < gi - (WIN - 1)) val = NEGF;
                    sacc[mf][nf][c] = val;
                    if (c & 2) mx1 = fmaxf(mx1, val);
                    else       mx0 = fmaxf(mx0, val);
                }
            }
            mx0 = fmaxf(mx0, __shfl_xor_sync(0xffffffffu, mx0, 1));
            mx0 = fmaxf(mx0, __shfl_xor_sync(0xffffffffu, mx0, 2));
            mx1 = fmaxf(mx1, __shfl_xor_sync(0xffffffffu, mx1, 1));
            mx1 = fmaxf(mx1, __shfl_xor_sync(0xffffffffu, mx1, 2));
            if (lq == 0) {
                partmx[rl0 * 4 + warp_n]       = mx0;
                partmx[(rl0 + 8) * 4 + warp_n] = mx1;
            }
        }
        __syncthreads();

        if (haveNext) {
            const int jn = j0 + 64;
#pragma unroll
            for (int i = 0; i < 8; i++) {
                const int u = tid + i * 256;
                const int r = u >> 5, ch = u & 31;
                const size_t go = ((size_t)kvh * S_LEN + jn + r) * HD + ch * 8;
                const uint32_t off = (uint32_t)r * (KROW * 4) + ch * 16;
                cp16(kb0 + off, g_kh + go);
                cp16(kb1 + off, g_kl + go);
            }
            cp_commit();
        }

#pragma unroll
        for (int mf = 0; mf < 2; mf++) {
            const int rl0 = warp_m * 32 + mf * 16 + lr;
            float t0 = fmaxf(fmaxf(partmx[rl0 * 4 + 0], partmx[rl0 * 4 + 1]),
                             fmaxf(partmx[rl0 * 4 + 2], partmx[rl0 * 4 + 3]));
            float t1 = fmaxf(fmaxf(partmx[(rl0 + 8) * 4 + 0], partmx[(rl0 + 8) * 4 + 1]),
                             fmaxf(partmx[(rl0 + 8) * 4 + 2], partmx[(rl0 + 8) * 4 + 3]));
            const float nm0 = fmaxf(M_[mf][0], t0);
            const float nm1 = fmaxf(M_[mf][1], t1);
            const float c0 = __expf(M_[mf][0] - nm0);
            const float c1 = __expf(M_[mf][1] - nm1);
            const float v0 = (nm0 > -1e37f) ? 1.f : 0.f;
            const float v1 = (nm1 > -1e37f) ? 1.f : 0.f;
            float ls0 = 0.f, ls1 = 0.f;
#pragma unroll
            for (int nf = 0; nf < 2; nf++) {
                float p0 = v0 * __expf(sacc[mf][nf][0] - nm0);
                float p1 = v0 * __expf(sacc[mf][nf][1] - nm0);
                float p2 = v1 * __expf(sacc[mf][nf][2] - nm1);
                float p3 = v1 * __expf(sacc[mf][nf][3] - nm1);
                ls0 += p0 + p1;
                ls1 += p2 + p3;
                const int cp = warp_n * 8 + nf * 4 + lq;
                ph32[rl0 * PSTR + cp]       = hipair(p0, p1);
                pl32[rl0 * PSTR + cp]       = lopair(p0, p1);
                ph32[(rl0 + 8) * PSTR + cp] = hipair(p2, p3);
                pl32[(rl0 + 8) * PSTR + cp] = lopair(p2, p3);
            }
            ls0 += __shfl_xor_sync(0xffffffffu, ls0, 1);
            ls0 += __shfl_xor_sync(0xffffffffu, ls0, 2);
            ls1 += __shfl_xor_sync(0xffffffffu, ls1, 1);
            ls1 += __shfl_xor_sync(0xffffffffu, ls1, 2);
            if (lq == 0) {
                partsm[rl0 * 4 + warp_n]       = ls0;
                partsm[(rl0 + 8) * 4 + warp_n] = ls1;
            }
#pragma unroll
            for (int nf = 0; nf < 8; nf++) {
                oacc[mf][nf][0] *= c0; oacc[mf][nf][1] *= c0;
                oacc[mf][nf][2] *= c1; oacc[mf][nf][3] *= c1;
            }
            M_[mf][0] = nm0; M_[mf][1] = nm1;
            pcorr[mf][0] = c0; pcorr[mf][1] = c1;
        }
        if (haveNext) cp_wait1(); else cp_wait0();
        __syncthreads();

#pragma unroll
        for (int mf = 0; mf < 2; mf++) {
            const int rl0 = warp_m * 32 + mf * 16 + lr;
            const float s0 = partsm[rl0 * 4 + 0] + partsm[rl0 * 4 + 1] +
                             partsm[rl0 * 4 + 2] + partsm[rl0 * 4 + 3];
            const float s1 = partsm[(rl0 + 8) * 4 + 0] + partsm[(rl0 + 8) * 4 + 1] +
                             partsm[(rl0 + 8) * 4 + 2] + partsm[(rl0 + 8) * 4 + 3];
            L_[mf][0] = L_[mf][0] * pcorr[mf][0] + s0;
            L_[mf][1] = L_[mf][1] * pcorr[mf][1] + s1;
        }

#pragma unroll
        for (int kj = 0; kj < 4; kj++) {
            uint32_t ah[2][4], al[2][4];
#pragma unroll
            for (int mf = 0; mf < 2; mf++) {
                const int r = warp_m * 32 + mf * 16 + lr;
                const int o = r * PSTR + kj * 8 + lq;
                ah[mf][0] = ph32[o];
                ah[mf][1] = ph32[o + 8 * PSTR];
                ah[mf][2] = ph32[o + 4];
                ah[mf][3] = ph32[o + 8 * PSTR + 4];
                al[mf][0] = pl32[o];
                al[mf][1] = pl32[o + 8 * PSTR];
                al[mf][2] = pl32[o + 4];
                al[mf][3] = pl32[o + 8 * PSTR + 4];
            }
#pragma unroll
            for (int nf = 0; nf < 8; nf++) {
                const int n = warp_n * 64 + nf * 8 + lr;
                const int o = n * VSTR + kj * 8 + lq;
                const uint32_t bh0 = v0s[o], bh1 = v0s[o + 4];
                const uint32_t bl0 = v1s[o], bl1 = v1s[o + 4];
#pragma unroll
                for (int mf = 0; mf < 2; mf++) {
                    mma_bf16(oacc[mf][nf], ah[mf][0], ah[mf][1], ah[mf][2], ah[mf][3], bh0, bh1);
                    mma_bf16(oacc[mf][nf], ah[mf][0], ah[mf][1], ah[mf][2], ah[mf][3], bl0, bl1);
                    mma_bf16(oacc[mf][nf], al[mf][0], al[mf][1], al[mf][2], al[mf][3], bh0, bh1);
                }
            }
        }
        __syncthreads();
    }

#pragma unroll
    for (int mf = 0; mf < 2; mf++) {
        const float i0 = 1.f / L_[mf][0];
        const float i1 = 1.f / L_[mf][1];
        const int r0 = m0 + warp_m * 32 + mf * 16 + lr;
#pragma unroll
        for (int nf = 0; nf < 8; nf++) {
            const int col = warp_n * 64 + nf * 8 + lq * 2;
            const size_t ix0 = (size_t)r0 * AO_N + h * HD + col;
            const size_t ix1 = ix0 + (size_t)8 * AO_N;
            const float a0 = oacc[mf][nf][0] * i0, a1 = oacc[mf][nf][1] * i0;
            const float b0 = oacc[mf][nf][2] * i1, b1 = oacc[mf][nf][3] * i1;
            *(uint32_t*)(g_ah + ix0) = hipair(a0, a1);
            *(uint32_t*)(g_al + ix0) = lopair(a0, a1);
            *(uint32_t*)(g_ah + ix1) = hipair(b0, b1);
            *(uint32_t*)(g_al + ix1) = lopair(b0, b1);
        }
    }
}

// ---------------------------------------------------------------------------
extern "C" void kernel_launch(void* const* d_in, const int* in_sizes, int n_in,
                              void* d_out, int out_size) {
    const float* hidden = (const float*)d_in[0];
    const float* freqs  = (const float*)d_in[1];
    const int*   widx   = (const int*)d_in[2];
    const float* qkv_w  = (const float*)d_in[6];
    const float* o_w    = (const float*)d_in[7];
    float* out = (float*)d_out;

    float *qkv_ptr, *hidT_ptr, *qwT_ptr;
    uint16_t *ah_ptr, *al_ptr, *wh_ptr, *wl_ptr;
    cudaGetSymbolAddress((void**)&qkv_ptr, g_qkv);
    cudaGetSymbolAddress((void**)&hidT_ptr, g_hidT);
    cudaGetSymbolAddress((void**)&qwT_ptr, g_qwT);
    cudaGetSymbolAddress((void**)&ah_ptr, g_ah);
    cudaGetSymbolAddress((void**)&al_ptr, g_al);
    cudaGetSymbolAddress((void**)&wh_ptr, g_wh);
    cudaGetSymbolAddress((void**)&wl_ptr, g_wl);

    cudaFuncSetAttribute(attn_mma,
                         cudaFuncAttributeMaxDynamicSharedMemorySize, ATTN_SMEM);
    cudaFuncSetAttribute(gemm_mma,
                         cudaFuncAttributeMaxDynamicSharedMemorySize, GEMM_SMEM);
    cudaFuncSetAttribute(gemm_bf3,
                         cudaFuncAttributeMaxDynamicSharedMemorySize, OGEMM_SMEM);

    // gemm_mma stays launch #4 (ncu capture slot)
    cvt_tf32_perm<<<1024, 256>>>(hidden, hidT_ptr, S_LEN * HID / 8);
    cvt_tf32_perm<<<2048, 256>>>(qkv_w, qwT_ptr, QKV_N * HID / 8);
    split_planes<<<1024, 256>>>(o_w, wh_ptr, wl_ptr, HID * AO_N / 4);
    gemm_mma<<<dim3(S_LEN / 128, QKV_N / 128), 256, GEMM_SMEM>>>(
        hidT_ptr, qwT_ptr, qkv_ptr, S_LEN, QKV_N, HID);
    rope_scatter<<<S_LEN, 256>>>(freqs, widx);
    transpose_split_v<<<dim3(S_LEN / 64, HD / 64, NKV), 256>>>();
    attn_mma<<<dim3(S_LEN / 64, NH), 256, ATTN_SMEM>>>();
    gemm_bf3<<<dim3(S_LEN / 128, HID / 128), 256, OGEMM_SMEM>>>(
        ah_ptr, al_ptr, wh_ptr, wl_ptr, out, S_LEN, HID, AO_N);
}

// round 14
// speedup vs baseline: 1.0744x; 1.0744x over previous
#include <cuda_runtime.h>
#include <cstdint>
#include <math.h>

#define S_LEN 3072
#define HID 3584
#define NH 16
#define NKV 8
#define HD 256
#define WIN 2048
#define QKV_N 8192
#define NEGF -2.3819763e38f
#define QSCALE 0.0625f
#define AO_N 4096
#define VOFF (NH * HD + NKV * HD)

typedef unsigned long long u64;

// ---------------- bf16 split helpers ----------------
__device__ __forceinline__ float hif(float a) {
    return __uint_as_float(__float_as_uint(a) & 0xFFFF0000u);
}
__device__ __forceinline__ uint32_t hipair(float a, float b) {
    uint32_t r;
    asm("prmt.b32 %0, %1, %2, 0x7632;"
        : "=r"(r) : "r"(__float_as_uint(a)), "r"(__float_as_uint(b)));
    return r;
}
__device__ __forceinline__ uint32_t lopair(float a, float b) {
    uint32_t r;
    asm("cvt.rn.bf16x2.f32 %0, %1, %2;"
        : "=r"(r) : "f"(b - hif(b)), "f"(a - hif(a)));
    return r;
}
__device__ __forceinline__ uint16_t hi16(float a) {
    return (uint16_t)(__float_as_uint(a) >> 16);
}
__device__ __forceinline__ uint16_t lo16(float a) {
    uint16_t u;
    asm("cvt.rn.bf16.f32 %0, %1;" : "=h"(u) : "f"(a - hif(a)));
    return u;
}

__device__ __forceinline__ void mma_bf16(float* c, uint32_t a0, uint32_t a1,
                                         uint32_t a2, uint32_t a3,
                                         uint32_t b0, uint32_t b1) {
    asm volatile(
        "mma.sync.aligned.m16n8k16.row.col.f32.bf16.bf16.f32 "
        "{%0,%1,%2,%3}, {%4,%5,%6,%7}, {%8,%9}, {%0,%1,%2,%3};"
        : "+f"(c[0]), "+f"(c[1]), "+f"(c[2]), "+f"(c[3])
        : "r"(a0), "r"(a1), "r"(a2), "r"(a3), "r"(b0), "r"(b1));
}

// ---------------- scratch ----------------
__device__ float g_qkv[S_LEN * QKV_N];
__device__ float g_hidT[S_LEN * HID];
__device__ float g_qwT[QKV_N * HID];
__device__ uint16_t g_kh[NKV * S_LEN * HD];
__device__ uint16_t g_kl[NKV * S_LEN * HD];
__device__ uint16_t g_vh[NKV * HD * S_LEN];
__device__ uint16_t g_vl[NKV * HD * S_LEN];
__device__ uint16_t g_ah[S_LEN * AO_N];
__device__ uint16_t g_al[S_LEN * AO_N];
__device__ uint16_t g_wh[HID * AO_N];
__device__ uint16_t g_wl[HID * AO_N];

// ---------------- common asm helpers ----------------
__device__ __forceinline__ uint32_t cvta_sh(const void* p) {
    uint32_t a;
    asm("{ .reg .u64 t; cvta.to.shared.u64 t, %1; cvt.u32.u64 %0, t; }"
        : "=r"(a) : "l"(p));
    return a;
}
__device__ __forceinline__ void cp16(uint32_t dst, const void* src) {
    asm volatile("cp.async.cg.shared.global [%0], [%1], 16;"
                 :: "r"(dst), "l"(src));
}
__device__ __forceinline__ void cp_commit() {
    asm volatile("cp.async.commit_group;" ::: "memory");
}
__device__ __forceinline__ void cp_wait1() {
    asm volatile("cp.async.wait_group 1;" ::: "memory");
}
__device__ __forceinline__ void cp_wait0() {
    asm volatile("cp.async.wait_group 0;" ::: "memory");
}
__device__ __forceinline__ uint32_t f2tf32(float x) {
    uint32_t r;
    asm("cvt.rna.tf32.f32 %0, %1;" : "=r"(r) : "f"(x));
    return r;
}
__device__ __forceinline__ void mma_tf32(float* c, const uint32_t* a,
                                         const uint32_t* b) {
    asm volatile(
        "mma.sync.aligned.m16n8k8.row.col.f32.tf32.tf32.f32 "
        "{%0,%1,%2,%3}, {%4,%5,%6,%7}, {%8,%9}, {%0,%1,%2,%3};"
        : "+f"(c[0]), "+f"(c[1]), "+f"(c[2]), "+f"(c[3])
        : "r"(a[0]), "r"(a[1]), "r"(a[2]), "r"(a[3]), "r"(b[0]), "r"(b[1]));
}

// =====================================================================
// fused pre-round fp32 -> tf32 for BOTH hidden and qkv_w
// =====================================================================
__global__ void __launch_bounds__(256) cvt_tf32_both(const float* __restrict__ s1,
                                                     float* __restrict__ d1, int n1,
                                                     const float* __restrict__ s2,
                                                     float* __restrict__ d2, int n2) {
    const int total = n1 + n2;
    for (int i = blockIdx.x * blockDim.x + threadIdx.x; i < total;
         i += gridDim.x * blockDim.x) {
        const float4* sp;
        float4* dp;
        int j;
        if (i < n1) { sp = (const float4*)s1; dp = (float4*)d1; j = i; }
        else        { sp = (const float4*)s2; dp = (float4*)d2; j = i - n1; }
        const float4 v = sp[j];
        float4 o;
        o.x = __uint_as_float(f2tf32(v.x));
        o.y = __uint_as_float(f2tf32(v.y));
        o.z = __uint_as_float(f2tf32(v.z));
        o.w = __uint_as_float(f2tf32(v.w));
        dp[j] = o;
    }
}

// =====================================================================
// tf32 mma.sync GEMM for QKV projection — R12 form (LDS.32), 2 CTAs/SM
// =====================================================================
#define GSTAGE 3
#define SROW 36
#define STAGE_FLOATS (128 * SROW)
#define STAGE_BYTES  (STAGE_FLOATS * 4 * 2)
#define GEMM_SMEM (GSTAGE * STAGE_BYTES)

__device__ __forceinline__ void g_load_stage(uint32_t smem_base,
                                             const float* __restrict__ A,
                                             const float* __restrict__ B,
                                             int K, int m0, int n0,
                                             int stage, int chunk, int tid) {
    const uint32_t sa = smem_base + stage * STAGE_BYTES;
    const uint32_t sb = sa + STAGE_FLOATS * 4;
    const float* Ab = A + (size_t)m0 * K + chunk * 32;
    const float* Bb = B + (size_t)n0 * K + chunk * 32;
#pragma unroll
    for (int i = 0; i < 4; i++) {
        const int u = tid + i * 256;
        const int r = u >> 3, ch = u & 7;
        const uint32_t off = (uint32_t)r * (SROW * 4) + ch * 16;
        cp16(sa + off, Ab + (size_t)r * K + ch * 4);
        cp16(sb + off, Bb + (size_t)r * K + ch * 4);
    }
    cp_commit();
}

__global__ void __launch_bounds__(256, 2) gemm_mma(const float* __restrict__ A,
                                                   const float* __restrict__ B,
                                                   float* __restrict__ C,
                                                   int M, int N, int K) {
    extern __shared__ __align__(16) char dynsm[];
    const int tid = threadIdx.x;
    const int wid = tid >> 5, lane = tid & 31;
    const int warp_m = wid & 1, warp_n = wid >> 1;
    const int m0 = blockIdx.x * 128, n0 = blockIdx.y * 128;
    const uint32_t smem_base = cvta_sh(dynsm);

    const int lr = lane >> 2;
    const int lc = lane & 3;

    float acc[4][4][4];
#pragma unroll
    for (int mi = 0; mi < 4; mi++)
#pragma unroll
        for (int ni = 0; ni < 4; ni++)
#pragma unroll
            for (int r = 0; r < 4; r++) acc[mi][ni][r] = 0.f;

    const int nk = K >> 5;

    g_load_stage(smem_base, A, B, K, m0, n0, 0, 0, tid);
    g_load_stage(smem_base, A, B, K, m0, n0, 1, 1, tid);

    for (int k0 = 0; k0 < nk; k0++) {
        cp_wait1();
        __syncthreads();
        if (k0 + 2 < nk)
            g_load_stage(smem_base, A, B, K, m0, n0, (k0 + 2) % GSTAGE,
                         k0 + 2, tid);

        const uint32_t* sA = (const uint32_t*)(dynsm + (size_t)(k0 % GSTAGE) * STAGE_BYTES);
        const uint32_t* sB = sA + STAGE_FLOATS;

#pragma unroll
        for (int ks = 0; ks < 4; ks++) {
            uint32_t af[4][4], bf[4][2];
#pragma unroll
            for (int mi = 0; mi < 4; mi++) {
                const int r = warp_m * 64 + mi * 16 + lr;
                const int c = ks * 8 + lc;
                af[mi][0] = sA[r * SROW + c];
                af[mi][1] = sA[(r + 8) * SROW + c];
                af[mi][2] = sA[r * SROW + c + 4];
                af[mi][3] = sA[(r + 8) * SROW + c + 4];
            }
#pragma unroll
            for (int ni = 0; ni < 4; ni++) {
                const int n = warp_n * 32 + ni * 8 + lr;
                const int c = ks * 8 + lc;
                bf[ni][0] = sB[n * SROW + c];
                bf[ni][1] = sB[n * SROW + c + 4];
            }
#pragma unroll
            for (int mi = 0; mi < 4; mi++)
#pragma unroll
                for (int ni = 0; ni < 4; ni++)
                    mma_tf32(acc[mi][ni], af[mi], bf[ni]);
        }
    }

#pragma unroll
    for (int mi = 0; mi < 4; mi++) {
        const int row0 = m0 + warp_m * 64 + mi * 16 + lr;
#pragma unroll
        for (int ni = 0; ni < 4; ni++) {
            const int col = n0 + warp_n * 32 + ni * 8 + 2 * lc;
            float* p0 = C + (size_t)row0 * N + col;
            float* p1 = p0 + 8 * N;
            *(float2*)p0 = make_float2(acc[mi][ni][0], acc[mi][ni][1]);
            *(float2*)p1 = make_float2(acc[mi][ni][2], acc[mi][ni][3]);
        }
    }
}

// =====================================================================
// split fp32 -> bf16 hi/lo planes (o_w only)
// =====================================================================
__global__ void __launch_bounds__(256) split_planes(const float* __restrict__ src,
                                                    uint16_t* __restrict__ hi,
                                                    uint16_t* __restrict__ lo,
                                                    int n4) {
    for (int i = blockIdx.x * blockDim.x + threadIdx.x; i < n4;
         i += gridDim.x * blockDim.x) {
        const float4 v = ((const float4*)src)[i];
        ushort4 h, l;
        h.x = hi16(v.x); h.y = hi16(v.y); h.z = hi16(v.z); h.w = hi16(v.w);
        l.x = lo16(v.x); l.y = lo16(v.y); l.z = lo16(v.z); l.w = lo16(v.w);
        ((ushort4*)hi)[i] = h;
        ((ushort4*)lo)[i] = l;
    }
}

// =====================================================================
// bf16x3 split GEMM for O-projection — 2-stage double buffer, 2 CTAs/SM
// =====================================================================
#define OSTAGE 2
#define BSTR 20
#define PLANE_W (128 * BSTR)
#define OSTG_BYTES (4 * PLANE_W * 4)
#define OGEMM_SMEM (OSTAGE * OSTG_BYTES)

__device__ __forceinline__ void o_load_stage(uint32_t smem_base,
                                             const uint16_t* __restrict__ Ah,
                                             const uint16_t* __restrict__ Al,
                                             const uint16_t* __restrict__ Bh,
                                             const uint16_t* __restrict__ Bl,
                                             int K, int m0, int n0,
                                             int stage, int chunk, int tid) {
    const uint32_t s0 = smem_base + stage * OSTG_BYTES;
    const uint16_t* p0 = Ah + (size_t)m0 * K + chunk * 32;
    const uint16_t* p1 = Al + (size_t)m0 * K + chunk * 32;
    const uint16_t* p2 = Bh + (size_t)n0 * K + chunk * 32;
    const uint16_t* p3 = Bl + (size_t)n0 * K + chunk * 32;
#pragma unroll
    for (int i = 0; i < 2; i++) {
        const int u = tid + i * 256;
        const int r = u >> 2, ch = u & 3;
        const uint32_t off = (uint32_t)r * (BSTR * 4) + ch * 16;
        const size_t go = (size_t)r * K + ch * 8;
        cp16(s0 + 0 * PLANE_W * 4 + off, p0 + go);
        cp16(s0 + 1 * PLANE_W * 4 + off, p1 + go);
        cp16(s0 + 2 * PLANE_W * 4 + off, p2 + go);
        cp16(s0 + 3 * PLANE_W * 4 + off, p3 + go);
    }
    cp_commit();
}

__global__ void __launch_bounds__(256, 2) gemm_bf3(const uint16_t* __restrict__ Ah,
                                                   const uint16_t* __restrict__ Al,
                                                   const uint16_t* __restrict__ Bh,
                                                   const uint16_t* __restrict__ Bl,
                                                   float* __restrict__ C,
                                                   int M, int N, int K) {
    extern __shared__ __align__(16) char dynsm[];
    const int tid = threadIdx.x;
    const int wid = tid >> 5, lane = tid & 31;
    const int warp_m = wid & 1, warp_n = wid >> 1;
    const int m0 = blockIdx.x * 128, n0 = blockIdx.y * 128;
    const uint32_t smem_base = cvta_sh(dynsm);

    const int lr = lane >> 2, lq = lane & 3;

    float acc[4][4][4];
#pragma unroll
    for (int mi = 0; mi < 4; mi++)
#pragma unroll
        for (int ni = 0; ni < 4; ni++)
#pragma unroll
            for (int r = 0; r < 4; r++) acc[mi][ni][r] = 0.f;

    const int nk = K >> 5;

    o_load_stage(smem_base, Ah, Al, Bh, Bl, K, m0, n0, 0, 0, tid);

    for (int k0 = 0; k0 < nk; k0++) {
        if (k0 + 1 < nk) {
            o_load_stage(smem_base, Ah, Al, Bh, Bl, K, m0, n0,
                         (k0 + 1) & 1, k0 + 1, tid);
            cp_wait1();
        } else {
            cp_wait0();
        }
        __syncthreads();

        const uint32_t* sAh = (const uint32_t*)(dynsm + (size_t)(k0 & 1) * OSTG_BYTES);
        const uint32_t* sAl = sAh + PLANE_W;
        const uint32_t* sBh = sAh + 2 * PLANE_W;
        const uint32_t* sBl = sAh + 3 * PLANE_W;

#pragma unroll
        for (int ks = 0; ks < 2; ks++) {
            uint32_t ah[4][4], al[4][4], bh[4][2], bl[4][2];
#pragma unroll
            for (int mi = 0; mi < 4; mi++) {
                const int r = warp_m * 64 + mi * 16 + lr;
                const int o = r * BSTR + ks * 8 + lq;
                ah[mi][0] = sAh[o];
                ah[mi][1] = sAh[o + 8 * BSTR];
                ah[mi][2] = sAh[o + 4];
                ah[mi][3] = sAh[o + 8 * BSTR + 4];
                al[mi][0] = sAl[o];
                al[mi][1] = sAl[o + 8 * BSTR];
                al[mi][2] = sAl[o + 4];
                al[mi][3] = sAl[o + 8 * BSTR + 4];
            }
#pragma unroll
            for (int ni = 0; ni < 4; ni++) {
                const int n = warp_n * 32 + ni * 8 + lr;
                const int o = n * BSTR + ks * 8 + lq;
                bh[ni][0] = sBh[o];
                bh[ni][1] = sBh[o + 4];
                bl[ni][0] = sBl[o];
                bl[ni][1] = sBl[o + 4];
            }
#pragma unroll
            for (int mi = 0; mi < 4; mi++)
#pragma unroll
                for (int ni = 0; ni < 4; ni++) {
                    mma_bf16(acc[mi][ni], ah[mi][0], ah[mi][1], ah[mi][2], ah[mi][3],
                             bh[ni][0], bh[ni][1]);
                    mma_bf16(acc[mi][ni], ah[mi][0], ah[mi][1], ah[mi][2], ah[mi][3],
                             bl[ni][0], bl[ni][1]);
                    mma_bf16(acc[mi][ni], al[mi][0], al[mi][1], al[mi][2], al[mi][3],
                             bh[ni][0], bh[ni][1]);
                }
        }
        __syncthreads();
    }

#pragma unroll
    for (int mi = 0; mi < 4; mi++) {
        const int row0 = m0 + warp_m * 64 + mi * 16 + lr;
#pragma unroll
        for (int ni = 0; ni < 4; ni++) {
            const int col = n0 + warp_n * 32 + ni * 8 + 2 * lq;
            float* p0 = C + (size_t)row0 * N + col;
            float* p1 = p0 + 8 * N;
            *(float2*)p0 = make_float2(acc[mi][ni][0], acc[mi][ni][1]);
            *(float2*)p1 = make_float2(acc[mi][ni][2], acc[mi][ni][3]);
        }
    }
}

// ---------------------------------------------------------------------------
// Fused prep: blocks [0, S_LEN) do RoPE (q in place, k -> bf16 planes);
// blocks [S_LEN, S_LEN + 1536) do the V transpose+split.
// ---------------------------------------------------------------------------
__global__ void __launch_bounds__(256) prep_fused(const float* __restrict__ freqs,
                                                  const int* __restrict__ widx) {
    __shared__ float sm[64][65];
    if (blockIdx.x < S_LEN) {
        const int l = blockIdx.x;
        const int t = threadIdx.x;
        const int dst = widx[l];
        const float* fr = freqs + (size_t)l * HD;
        float* row = g_qkv + (size_t)l * QKV_N;

        for (int p = t; p < NH * 128; p += 256) {
            const int hh = p >> 7, d = p & 127;
            const float c = fr[2 * d], s = fr[2 * d + 1];
            float* q = row + hh * HD;
            const float x1 = q[d], x2 = q[d + 128];
            q[d]       = (x1 * c - x2 * s) * QSCALE;
            q[d + 128] = (x1 * s + x2 * c) * QSCALE;
        }
        for (int p = t; p < NKV * 128; p += 256) {
            const int hh = p >> 7, d = p & 127;
            const float c = fr[2 * d], s = fr[2 * d + 1];
            const float* kk = row + NH * HD + hh * HD;
            const float x1 = kk[d], x2 = kk[d + 128];
            const float y1 = x1 * c - x2 * s;
            const float y2 = x1 * s + x2 * c;
            const size_t base = ((size_t)hh * S_LEN + dst) * HD;
            g_kh[base + d]       = hi16(y1);
            g_kh[base + d + 128] = hi16(y2);
            g_kl[base + d]       = lo16(y1);
            g_kl[base + d + 128] = lo16(y2);
        }
    } else {
        const int idx = blockIdx.x - S_LEN;           // 0..1535
        const int j0 = (idx % 48) * 64;
        const int d0 = ((idx / 48) & 3) * 64;
        const int kvh = idx / 192;
        const int t = threadIdx.x;
#pragma unroll
        for (int i = 0; i < 16; i++) {
            const int id = t + i * 256;
            const int jr = id >> 6, dc = id & 63;
            sm[jr][dc] = g_qkv[(size_t)(j0 + jr) * QKV_N + VOFF + kvh * HD + d0 + dc];
        }
        __syncthreads();
#pragma unroll
        for (int i = 0; i < 8; i++) {
            const int id = t + i * 256;
            const int dr = id >> 5, jp = id & 31;
            const float f0 = sm[jp * 2][dr];
            const float f1 = sm[jp * 2 + 1][dr];
            const size_t go = ((size_t)kvh * HD + d0 + dr) * S_LEN + j0 + jp * 2;
            ushort2 h, l;
            h.x = hi16(f0); h.y = hi16(f1);
            l.x = lo16(f0); l.y = lo16(f1);
            *(ushort2*)(g_vh + go) = h;
            *(ushort2*)(g_vl + go) = l;
        }
    }
}

// =====================================================================
// Flash attention (R11/R12 config): 256 threads, heavy-first ordering.
// =====================================================================
#define QSTR 132
#define KROW 132
#define VSTR 36
#define PSTR 36
#define N_Q (64 * QSTR)
#define N_K (64 * KROW)
#define N_V (256 * VSTR)
#define N_P (64 * PSTR)
#define ATTN_SMEM ((2 * N_Q + 2 * N_K + 2 * N_V + 2 * N_P + 512) * 4)

__global__ void __launch_bounds__(256, 1) attn_mma() {
    extern __shared__ __align__(16) char smraw[];
    uint32_t* qh32 = (uint32_t*)smraw;
    uint32_t* ql32 = qh32 + N_Q;
    uint32_t* k0s  = ql32 + N_Q;
    uint32_t* k1s  = k0s + N_K;
    uint32_t* v0s  = k1s + N_K;
    uint32_t* v1s  = v0s + N_V;
    uint32_t* ph32 = v1s + N_V;
    uint32_t* pl32 = ph32 + N_P;
    float* partmx = (float*)(pl32 + N_P);
    float* partsm = partmx + 256;

    const uint32_t smem_base = cvta_sh(smraw);
    const uint32_t kb0 = smem_base + (2 * N_Q) * 4;
    const uint32_t kb1 = kb0 + N_K * 4;
    const uint32_t vb0 = kb1 + N_K * 4;
    const uint32_t vb1 = vb0 + N_V * 4;

    const int tid = threadIdx.x;
    const int lane = tid & 31, wid = tid >> 5;
    const int warp_m = wid & 1, warp_n = wid >> 1;
    const int lr = lane >> 2, lq = lane & 3;
    const int h = blockIdx.y, kvh = h >> 1;
    const int bx = gridDim.x - 1 - blockIdx.x;
    const int m0 = bx * 64;

    {
        const int row = tid >> 2, cb = (tid & 3) * 64;
        const float* q = g_qkv + (size_t)(m0 + row) * QKV_N + h * HD + cb;
#pragma unroll
        for (int i = 0; i < 16; i++) {
            const float4 v = *(const float4*)(q + i * 4);
            const int cp = (cb + i * 4) >> 1;
            qh32[row * QSTR + cp]     = hipair(v.x, v.y);
            qh32[row * QSTR + cp + 1] = hipair(v.z, v.w);
            ql32[row * QSTR + cp]     = lopair(v.x, v.y);
            ql32[row * QSTR + cp + 1] = lopair(v.z, v.w);
        }
    }

    float M_[2][2], L_[2][2], pcorr[2][2];
#pragma unroll
    for (int a = 0; a < 2; a++)
#pragma unroll
        for (int b = 0; b < 2; b++) { M_[a][b] = NEGF; L_[a][b] = 0.f; }

    float oacc[2][8][4];
#pragma unroll
    for (int mf = 0; mf < 2; mf++)
#pragma unroll
        for (int nf = 0; nf < 8; nf++)
#pragma unroll
            for (int c = 0; c < 4; c++) oacc[mf][nf][c] = 0.f;

    int lo = m0 - (WIN - 1);
    if (lo < 0) lo = 0;
    const int jt0 = lo >> 6, jt1 = bx;

    {
        const int j0 = jt0 * 64;
#pragma unroll
        for (int i = 0; i < 8; i++) {
            const int u = tid + i * 256;
            const int r = u >> 5, ch = u & 31;
            const size_t go = ((size_t)kvh * S_LEN + j0 + r) * HD + ch * 8;
            const uint32_t off = (uint32_t)r * (KROW * 4) + ch * 16;
            cp16(kb0 + off, g_kh + go);
            cp16(kb1 + off, g_kl + go);
        }
        cp_commit();
    }

    for (int jt = jt0; jt <= jt1; jt++) {
        const int j0 = jt * 64;
        const bool haveNext = (jt < jt1);

#pragma unroll
        for (int i = 0; i < 8; i++) {
            const int u = tid + i * 256;
            const int r = u >> 3, ch = u & 7;
            const size_t go = ((size_t)kvh * HD + r) * S_LEN + j0 + ch * 8;
            const uint32_t off = (uint32_t)r * (VSTR * 4) + ch * 16;
            cp16(vb0 + off, g_vh + go);
            cp16(vb1 + off, g_vl + go);
        }
        cp_commit();

        cp_wait1();
        __syncthreads();

        float sacc[2][2][4];
#pragma unroll
        for (int mf = 0; mf < 2; mf++)
#pragma unroll
            for (int nf = 0; nf < 2; nf++)
#pragma unroll
                for (int c = 0; c < 4; c++) sacc[mf][nf][c] = 0.f;

#pragma unroll
        for (int ks = 0; ks < 16; ks++) {
            uint32_t ah[2][4], al[2][4];
#pragma unroll
            for (int mf = 0; mf < 2; mf++) {
                const int r = warp_m * 32 + mf * 16 + lr;
                const int o = r * QSTR + ks * 8 + lq;
                ah[mf][0] = qh32[o];
                ah[mf][1] = qh32[o + 8 * QSTR];
                ah[mf][2] = qh32[o + 4];
                ah[mf][3] = qh32[o + 8 * QSTR + 4];
                al[mf][0] = ql32[o];
                al[mf][1] = ql32[o + 8 * QSTR];
                al[mf][2] = ql32[o + 4];
                al[mf][3] = ql32[o + 8 * QSTR + 4];
            }
#pragma unroll
            for (int nf = 0; nf < 2; nf++) {
                const int n = warp_n * 16 + nf * 8 + lr;
                const int o = n * KROW + ks * 8 + lq;
                const uint32_t bh0 = k0s[o], bh1 = k0s[o + 4];
                const uint32_t bl0 = k1s[o], bl1 = k1s[o + 4];
#pragma unroll
                for (int mf = 0; mf < 2; mf++) {
                    mma_bf16(sacc[mf][nf], ah[mf][0], ah[mf][1], ah[mf][2], ah[mf][3], bh0, bh1);
                    mma_bf16(sacc[mf][nf], ah[mf][0], ah[mf][1], ah[mf][2], ah[mf][3], bl0, bl1);
                    mma_bf16(sacc[mf][nf], al[mf][0], al[mf][1], al[mf][2], al[mf][3], bh0, bh1);
                }
            }
        }

#pragma unroll
        for (int mf = 0; mf < 2; mf++) {
            const int rl0 = warp_m * 32 + mf * 16 + lr;
            float mx0 = NEGF, mx1 = NEGF;
#pragma unroll
            for (int nf = 0; nf < 2; nf++) {
#pragma unroll
                for (int c = 0; c < 4; c++) {
                    const float s = sacc[mf][nf][c];
                    const float e = __expf(s * 0.04f);
                    float val = 50.f - 100.f / (e + 1.f);
                    const int gj = j0 + warp_n * 16 + nf * 8 + lq * 2 + (c & 1);
                    const int gi = m0 + rl0 + ((c & 2) ? 8 : 0);
                    if (gj > gi || gj < gi - (WIN - 1)) val = NEGF;
                    sacc[mf][nf][c] = val;
                    if (c & 2) mx1 = fmaxf(mx1, val);
                    else       mx0 = fmaxf(mx0, val);
                }
            }
            mx0 = fmaxf(mx0, __shfl_xor_sync(0xffffffffu, mx0, 1));
            mx0 = fmaxf(mx0, __shfl_xor_sync(0xffffffffu, mx0, 2));
            mx1 = fmaxf(mx1, __shfl_xor_sync(0xffffffffu, mx1, 1));
            mx1 = fmaxf(mx1, __shfl_xor_sync(0xffffffffu, mx1, 2));
            if (lq == 0) {
                partmx[rl0 * 4 + warp_n]       = mx0;
                partmx[(rl0 + 8) * 4 + warp_n] = mx1;
            }
        }
        __syncthreads();

        if (haveNext) {
            const int jn = j0 + 64;
#pragma unroll
            for (int i = 0; i < 8; i++) {
                const int u = tid + i * 256;
                const int r = u >> 5, ch = u & 31;
                const size_t go = ((size_t)kvh * S_LEN + jn + r) * HD + ch * 8;
                const uint32_t off = (uint32_t)r * (KROW * 4) + ch * 16;
                cp16(kb0 + off, g_kh + go);
                cp16(kb1 + off, g_kl + go);
            }
            cp_commit();
        }

#pragma unroll
        for (int mf = 0; mf < 2; mf++) {
            const int rl0 = warp_m * 32 + mf * 16 + lr;
            float t0 = fmaxf(fmaxf(partmx[rl0 * 4 + 0], partmx[rl0 * 4 + 1]),
                             fmaxf(partmx[rl0 * 4 + 2], partmx[rl0 * 4 + 3]));
            float t1 = fmaxf(fmaxf(partmx[(rl0 + 8) * 4 + 0], partmx[(rl0 + 8) * 4 + 1]),
                             fmaxf(partmx[(rl0 + 8) * 4 + 2], partmx[(rl0 + 8) * 4 + 3]));
            const float nm0 = fmaxf(M_[mf][0], t0);
            const float nm1 = fmaxf(M_[mf][1], t1);
            const float c0 = __expf(M_[mf][0] - nm0);
            const float c1 = __expf(M_[mf][1] - nm1);
            const float v0 = (nm0 > -1e37f) ? 1.f : 0.f;
            const float v1 = (nm1 > -1e37f) ? 1.f : 0.f;
            float ls0 = 0.f, ls1 = 0.f;
#pragma unroll
            for (int nf = 0; nf < 2; nf++) {
                float p0 = v0 * __expf(sacc[mf][nf][0] - nm0);
                float p1 = v0 * __expf(sacc[mf][nf][1] - nm0);
                float p2 = v1 * __expf(sacc[mf][nf][2] - nm1);
                float p3 = v1 * __expf(sacc[mf][nf][3] - nm1);
                ls0 += p0 + p1;
                ls1 += p2 + p3;
                const int cp = warp_n * 8 + nf * 4 + lq;
                ph32[rl0 * PSTR + cp]       = hipair(p0, p1);
                pl32[rl0 * PSTR + cp]       = lopair(p0, p1);
                ph32[(rl0 + 8) * PSTR + cp] = hipair(p2, p3);
                pl32[(rl0 + 8) * PSTR + cp] = lopair(p2, p3);
            }
            ls0 += __shfl_xor_sync(0xffffffffu, ls0, 1);
            ls0 += __shfl_xor_sync(0xffffffffu, ls0, 2);
            ls1 += __shfl_xor_sync(0xffffffffu, ls1, 1);
            ls1 += __shfl_xor_sync(0xffffffffu, ls1, 2);
            if (lq == 0) {
                partsm[rl0 * 4 + warp_n]       = ls0;
                partsm[(rl0 + 8) * 4 + warp_n] = ls1;
            }
#pragma unroll
            for (int nf = 0; nf < 8; nf++) {
                oacc[mf][nf][0] *= c0; oacc[mf][nf][1] *= c0;
                oacc[mf][nf][2] *= c1; oacc[mf][nf][3] *= c1;
            }
            M_[mf][0] = nm0; M_[mf][1] = nm1;
            pcorr[mf][0] = c0; pcorr[mf][1] = c1;
        }
        if (haveNext) cp_wait1(); else cp_wait0();
        __syncthreads();

#pragma unroll
        for (int mf = 0; mf < 2; mf++) {
            const int rl0 = warp_m * 32 + mf * 16 + lr;
            const float s0 = partsm[rl0 * 4 + 0] + partsm[rl0 * 4 + 1] +
                             partsm[rl0 * 4 + 2] + partsm[rl0 * 4 + 3];
            const float s1 = partsm[(rl0 + 8) * 4 + 0] + partsm[(rl0 + 8) * 4 + 1] +
                             partsm[(rl0 + 8) * 4 + 2] + partsm[(rl0 + 8) * 4 + 3];
            L_[mf][0] = L_[mf][0] * pcorr[mf][0] + s0;
            L_[mf][1] = L_[mf][1] * pcorr[mf][1] + s1;
        }

#pragma unroll
        for (int kj = 0; kj < 4; kj++) {
            uint32_t ah[2][4], al[2][4];
#pragma unroll
            for (int mf = 0; mf < 2; mf++) {
                const int r = warp_m * 32 + mf * 16 + lr;
                const int o = r * PSTR + kj * 8 + lq;
                ah[mf][0] = ph32[o];
                ah[mf][1] = ph32[o + 8 * PSTR];
                ah[mf][2] = ph32[o + 4];
                ah[mf][3] = ph32[o + 8 * PSTR + 4];
                al[mf][0] = pl32[o];
                al[mf][1] = pl32[o + 8 * PSTR];
                al[mf][2] = pl32[o + 4];
                al[mf][3] = pl32[o + 8 * PSTR + 4];
            }
#pragma unroll
            for (int nf = 0; nf < 8; nf++) {
                const int n = warp_n * 64 + nf * 8 + lr;
                const int o = n * VSTR + kj * 8 + lq;
                const uint32_t bh0 = v0s[o], bh1 = v0s[o + 4];
                const uint32_t bl0 = v1s[o], bl1 = v1s[o + 4];
#pragma unroll
                for (int mf = 0; mf < 2; mf++) {
                    mma_bf16(oacc[mf][nf], ah[mf][0], ah[mf][1], ah[mf][2], ah[mf][3], bh0, bh1);
                    mma_bf16(oacc[mf][nf], ah[mf][0], ah[mf][1], ah[mf][2], ah[mf][3], bl0, bl1);
                    mma_bf16(oacc[mf][nf], al[mf][0], al[mf][1], al[mf][2], al[mf][3], bh0, bh1);
                }
            }
        }
        __syncthreads();
    }

#pragma unroll
    for (int mf = 0; mf < 2; mf++) {
        const float i0 = 1.f / L_[mf][0];
        const float i1 = 1.f / L_[mf][1];
        const int r0 = m0 + warp_m * 32 + mf * 16 + lr;
#pragma unroll
        for (int nf = 0; nf < 8; nf++) {
            const int col = warp_n * 64 + nf * 8 + lq * 2;
            const size_t ix0 = (size_t)r0 * AO_N + h * HD + col;
            const size_t ix1 = ix0 + (size_t)8 * AO_N;
            const float a0 = oacc[mf][nf][0] * i0, a1 = oacc[mf][nf][1] * i0;
            const float b0 = oacc[mf][nf][2] * i1, b1 = oacc[mf][nf][3] * i1;
            *(uint32_t*)(g_ah + ix0) = hipair(a0, a1);
            *(uint32_t*)(g_al + ix0) = lopair(a0, a1);
            *(uint32_t*)(g_ah + ix1) = hipair(b0, b1);
            *(uint32_t*)(g_al + ix1) = lopair(b0, b1);
        }
    }
}

// ---------------------------------------------------------------------------
extern "C" void kernel_launch(void* const* d_in, const int* in_sizes, int n_in,
                              void* d_out, int out_size) {
    const float* hidden = (const float*)d_in[0];
    const float* freqs  = (const float*)d_in[1];
    const int*   widx   = (const int*)d_in[2];
    const float* qkv_w  = (const float*)d_in[6];
    const float* o_w    = (const float*)d_in[7];
    float* out = (float*)d_out;

    float *qkv_ptr, *hidT_ptr, *qwT_ptr;
    uint16_t *ah_ptr, *al_ptr, *wh_ptr, *wl_ptr;
    cudaGetSymbolAddress((void**)&qkv_ptr, g_qkv);
    cudaGetSymbolAddress((void**)&hidT_ptr, g_hidT);
    cudaGetSymbolAddress((void**)&qwT_ptr, g_qwT);
    cudaGetSymbolAddress((void**)&ah_ptr, g_ah);
    cudaGetSymbolAddress((void**)&al_ptr, g_al);
    cudaGetSymbolAddress((void**)&wh_ptr, g_wh);
    cudaGetSymbolAddress((void**)&wl_ptr, g_wl);

    cudaFuncSetAttribute(attn_mma,
                         cudaFuncAttributeMaxDynamicSharedMemorySize, ATTN_SMEM);
    cudaFuncSetAttribute(gemm_mma,
                         cudaFuncAttributeMaxDynamicSharedMemorySize, GEMM_SMEM);
    cudaFuncSetAttribute(gemm_bf3,
                         cudaFuncAttributeMaxDynamicSharedMemorySize, OGEMM_SMEM);

    // attn_mma is launch #4 (ncu capture slot)
    cvt_tf32_both<<<2048, 256>>>(hidden, hidT_ptr, S_LEN * HID / 4,
                                 qkv_w, qwT_ptr, QKV_N * HID / 4);
    gemm_mma<<<dim3(S_LEN / 128, QKV_N / 128), 256, GEMM_SMEM>>>(
        hidT_ptr, qwT_ptr, qkv_ptr, S_LEN, QKV_N, HID);
    prep_fused<<<S_LEN + 1536, 256>>>(freqs, widx);
    attn_mma<<<dim3(S_LEN / 64, NH), 256, ATTN_SMEM>>>();
    split_planes<<<1024, 256>>>(o_w, wh_ptr, wl_ptr, HID * AO_N / 4);
    gemm_bf3<<<dim3(S_LEN / 128, HID / 128), 256, OGEMM_SMEM>>>(
        ah_ptr, al_ptr, wh_ptr, wl_ptr, out, S_LEN, HID, AO_N);
}

// round 15
// speedup vs baseline: 1.0875x; 1.0123x over previous
#include <cuda_runtime.h>
#include <cstdint>
#include <math.h>

#define S_LEN 3072
#define HID 3584
#define NH 16
#define NKV 8
#define HD 256
#define WIN 2048
#define QKV_N 8192
#define NEGF -2.3819763e38f
#define QSCALE 0.0625f
#define AO_N 4096
#define VOFF (NH * HD + NKV * HD)

typedef unsigned long long u64;

// ---------------- bf16 split helpers ----------------
__device__ __forceinline__ float hif(float a) {
    return __uint_as_float(__float_as_uint(a) & 0xFFFF0000u);
}
__device__ __forceinline__ uint32_t hipair(float a, float b) {
    uint32_t r;
    asm("prmt.b32 %0, %1, %2, 0x7632;"
        : "=r"(r) : "r"(__float_as_uint(a)), "r"(__float_as_uint(b)));
    return r;
}
__device__ __forceinline__ uint32_t lopair(float a, float b) {
    uint32_t r;
    asm("cvt.rn.bf16x2.f32 %0, %1, %2;"
        : "=r"(r) : "f"(b - hif(b)), "f"(a - hif(a)));
    return r;
}
__device__ __forceinline__ uint16_t hi16(float a) {
    return (uint16_t)(__float_as_uint(a) >> 16);
}
__device__ __forceinline__ uint16_t lo16(float a) {
    uint16_t u;
    asm("cvt.rn.bf16.f32 %0, %1;" : "=h"(u) : "f"(a - hif(a)));
    return u;
}

__device__ __forceinline__ void mma_bf16(float* c, uint32_t a0, uint32_t a1,
                                         uint32_t a2, uint32_t a3,
                                         uint32_t b0, uint32_t b1) {
    asm volatile(
        "mma.sync.aligned.m16n8k16.row.col.f32.bf16.bf16.f32 "
        "{%0,%1,%2,%3}, {%4,%5,%6,%7}, {%8,%9}, {%0,%1,%2,%3};"
        : "+f"(c[0]), "+f"(c[1]), "+f"(c[2]), "+f"(c[3])
        : "r"(a0), "r"(a1), "r"(a2), "r"(a3), "r"(b0), "r"(b1));
}

// ---------------- scratch ----------------
__device__ float g_qkv[S_LEN * QKV_N];
__device__ float g_hidT[S_LEN * HID];
__device__ float g_qwT[QKV_N * HID];
__device__ uint16_t g_kh[NKV * S_LEN * HD];
__device__ uint16_t g_kl[NKV * S_LEN * HD];
__device__ uint16_t g_vh[NKV * HD * S_LEN];
__device__ uint16_t g_vl[NKV * HD * S_LEN];
__device__ uint16_t g_ah[S_LEN * AO_N];
__device__ uint16_t g_al[S_LEN * AO_N];
__device__ uint16_t g_wh[HID * AO_N];
__device__ uint16_t g_wl[HID * AO_N];

// ---------------- common asm helpers ----------------
__device__ __forceinline__ uint32_t cvta_sh(const void* p) {
    uint32_t a;
    asm("{ .reg .u64 t; cvta.to.shared.u64 t, %1; cvt.u32.u64 %0, t; }"
        : "=r"(a) : "l"(p));
    return a;
}
__device__ __forceinline__ void cp16(uint32_t dst, const void* src) {
    asm volatile("cp.async.cg.shared.global [%0], [%1], 16;"
                 :: "r"(dst), "l"(src));
}
__device__ __forceinline__ void cp_commit() {
    asm volatile("cp.async.commit_group;" ::: "memory");
}
__device__ __forceinline__ void cp_wait1() {
    asm volatile("cp.async.wait_group 1;" ::: "memory");
}
__device__ __forceinline__ void cp_wait0() {
    asm volatile("cp.async.wait_group 0;" ::: "memory");
}
__device__ __forceinline__ uint32_t f2tf32(float x) {
    uint32_t r;
    asm("cvt.rna.tf32.f32 %0, %1;" : "=r"(r) : "f"(x));
    return r;
}
__device__ __forceinline__ void mma_tf32(float* c, const uint32_t* a,
                                         const uint32_t* b) {
    asm volatile(
        "mma.sync.aligned.m16n8k8.row.col.f32.tf32.tf32.f32 "
        "{%0,%1,%2,%3}, {%4,%5,%6,%7}, {%8,%9}, {%0,%1,%2,%3};"
        : "+f"(c[0]), "+f"(c[1]), "+f"(c[2]), "+f"(c[3])
        : "r"(a[0]), "r"(a[1]), "r"(a[2]), "r"(a[3]), "r"(b[0]), "r"(b[1]));
}

// =====================================================================
// fused pre-round fp32 -> tf32 for BOTH hidden and qkv_w
// =====================================================================
__global__ void __launch_bounds__(256) cvt_tf32_both(const float* __restrict__ s1,
                                                     float* __restrict__ d1, int n1,
                                                     const float* __restrict__ s2,
                                                     float* __restrict__ d2, int n2) {
    const int total = n1 + n2;
    for (int i = blockIdx.x * blockDim.x + threadIdx.x; i < total;
         i += gridDim.x * blockDim.x) {
        const float4* sp;
        float4* dp;
        int j;
        if (i < n1) { sp = (const float4*)s1; dp = (float4*)d1; j = i; }
        else        { sp = (const float4*)s2; dp = (float4*)d2; j = i - n1; }
        const float4 v = sp[j];
        float4 o;
        o.x = __uint_as_float(f2tf32(v.x));
        o.y = __uint_as_float(f2tf32(v.y));
        o.z = __uint_as_float(f2tf32(v.z));
        o.w = __uint_as_float(f2tf32(v.w));
        dp[j] = o;
    }
}

// =====================================================================
// tf32 mma.sync GEMM for QKV projection — 2 CTAs/SM
// =====================================================================
#define GSTAGE 3
#define SROW 36
#define STAGE_FLOATS (128 * SROW)
#define STAGE_BYTES  (STAGE_FLOATS * 4 * 2)
#define GEMM_SMEM (GSTAGE * STAGE_BYTES)

__device__ __forceinline__ void g_load_stage(uint32_t smem_base,
                                             const float* __restrict__ A,
                                             const float* __restrict__ B,
                                             int K, int m0, int n0,
                                             int stage, int chunk, int tid) {
    const uint32_t sa = smem_base + stage * STAGE_BYTES;
    const uint32_t sb = sa + STAGE_FLOATS * 4;
    const float* Ab = A + (size_t)m0 * K + chunk * 32;
    const float* Bb = B + (size_t)n0 * K + chunk * 32;
#pragma unroll
    for (int i = 0; i < 4; i++) {
        const int u = tid + i * 256;
        const int r = u >> 3, ch = u & 7;
        const uint32_t off = (uint32_t)r * (SROW * 4) + ch * 16;
        cp16(sa + off, Ab + (size_t)r * K + ch * 4);
        cp16(sb + off, Bb + (size_t)r * K + ch * 4);
    }
    cp_commit();
}

__global__ void __launch_bounds__(256, 2) gemm_mma(const float* __restrict__ A,
                                                   const float* __restrict__ B,
                                                   float* __restrict__ C,
                                                   int M, int N, int K) {
    extern __shared__ __align__(16) char dynsm[];
    const int tid = threadIdx.x;
    const int wid = tid >> 5, lane = tid & 31;
    const int warp_m = wid & 1, warp_n = wid >> 1;
    const int m0 = blockIdx.x * 128, n0 = blockIdx.y * 128;
    const uint32_t smem_base = cvta_sh(dynsm);

    const int lr = lane >> 2;
    const int lc = lane & 3;

    float acc[4][4][4];
#pragma unroll
    for (int mi = 0; mi < 4; mi++)
#pragma unroll
        for (int ni = 0; ni < 4; ni++)
#pragma unroll
            for (int r = 0; r < 4; r++) acc[mi][ni][r] = 0.f;

    const int nk = K >> 5;

    g_load_stage(smem_base, A, B, K, m0, n0, 0, 0, tid);
    g_load_stage(smem_base, A, B, K, m0, n0, 1, 1, tid);

    for (int k0 = 0; k0 < nk; k0++) {
        cp_wait1();
        __syncthreads();
        if (k0 + 2 < nk)
            g_load_stage(smem_base, A, B, K, m0, n0, (k0 + 2) % GSTAGE,
                         k0 + 2, tid);

        const uint32_t* sA = (const uint32_t*)(dynsm + (size_t)(k0 % GSTAGE) * STAGE_BYTES);
        const uint32_t* sB = sA + STAGE_FLOATS;

#pragma unroll
        for (int ks = 0; ks < 4; ks++) {
            uint32_t af[4][4], bf[4][2];
#pragma unroll
            for (int mi = 0; mi < 4; mi++) {
                const int r = warp_m * 64 + mi * 16 + lr;
                const int c = ks * 8 + lc;
                af[mi][0] = sA[r * SROW + c];
                af[mi][1] = sA[(r + 8) * SROW + c];
                af[mi][2] = sA[r * SROW + c + 4];
                af[mi][3] = sA[(r + 8) * SROW + c + 4];
            }
#pragma unroll
            for (int ni = 0; ni < 4; ni++) {
                const int n = warp_n * 32 + ni * 8 + lr;
                const int c = ks * 8 + lc;
                bf[ni][0] = sB[n * SROW + c];
                bf[ni][1] = sB[n * SROW + c + 4];
            }
#pragma unroll
            for (int mi = 0; mi < 4; mi++)
#pragma unroll
                for (int ni = 0; ni < 4; ni++)
                    mma_tf32(acc[mi][ni], af[mi], bf[ni]);
        }
    }

#pragma unroll
    for (int mi = 0; mi < 4; mi++) {
        const int row0 = m0 + warp_m * 64 + mi * 16 + lr;
#pragma unroll
        for (int ni = 0; ni < 4; ni++) {
            const int col = n0 + warp_n * 32 + ni * 8 + 2 * lc;
            float* p0 = C + (size_t)row0 * N + col;
            float* p1 = p0 + 8 * N;
            *(float2*)p0 = make_float2(acc[mi][ni][0], acc[mi][ni][1]);
            *(float2*)p1 = make_float2(acc[mi][ni][2], acc[mi][ni][3]);
        }
    }
}

// =====================================================================
// split fp32 -> bf16 hi/lo planes (o_w only)
// =====================================================================
__global__ void __launch_bounds__(256) split_planes(const float* __restrict__ src,
                                                    uint16_t* __restrict__ hi,
                                                    uint16_t* __restrict__ lo,
                                                    int n4) {
    for (int i = blockIdx.x * blockDim.x + threadIdx.x; i < n4;
         i += gridDim.x * blockDim.x) {
        const float4 v = ((const float4*)src)[i];
        ushort4 h, l;
        h.x = hi16(v.x); h.y = hi16(v.y); h.z = hi16(v.z); h.w = hi16(v.w);
        l.x = lo16(v.x); l.y = lo16(v.y); l.z = lo16(v.z); l.w = lo16(v.w);
        ((ushort4*)hi)[i] = h;
        ((ushort4*)lo)[i] = l;
    }
}

// =====================================================================
// bf16x3 split GEMM for O-projection — 2-stage double buffer, 2 CTAs/SM
// =====================================================================
#define OSTAGE 2
#define BSTR 20
#define PLANE_W (128 * BSTR)
#define OSTG_BYTES (4 * PLANE_W * 4)
#define OGEMM_SMEM (OSTAGE * OSTG_BYTES)

__device__ __forceinline__ void o_load_stage(uint32_t smem_base,
                                             const uint16_t* __restrict__ Ah,
                                             const uint16_t* __restrict__ Al,
                                             const uint16_t* __restrict__ Bh,
                                             const uint16_t* __restrict__ Bl,
                                             int K, int m0, int n0,
                                             int stage, int chunk, int tid) {
    const uint32_t s0 = smem_base + stage * OSTG_BYTES;
    const uint16_t* p0 = Ah + (size_t)m0 * K + chunk * 32;
    const uint16_t* p1 = Al + (size_t)m0 * K + chunk * 32;
    const uint16_t* p2 = Bh + (size_t)n0 * K + chunk * 32;
    const uint16_t* p3 = Bl + (size_t)n0 * K + chunk * 32;
#pragma unroll
    for (int i = 0; i < 2; i++) {
        const int u = tid + i * 256;
        const int r = u >> 2, ch = u & 3;
        const uint32_t off = (uint32_t)r * (BSTR * 4) + ch * 16;
        const size_t go = (size_t)r * K + ch * 8;
        cp16(s0 + 0 * PLANE_W * 4 + off, p0 + go);
        cp16(s0 + 1 * PLANE_W * 4 + off, p1 + go);
        cp16(s0 + 2 * PLANE_W * 4 + off, p2 + go);
        cp16(s0 + 3 * PLANE_W * 4 + off, p3 + go);
    }
    cp_commit();
}

__global__ void __launch_bounds__(256, 2) gemm_bf3(const uint16_t* __restrict__ Ah,
                                                   const uint16_t* __restrict__ Al,
                                                   const uint16_t* __restrict__ Bh,
                                                   const uint16_t* __restrict__ Bl,
                                                   float* __restrict__ C,
                                                   int M, int N, int K) {
    extern __shared__ __align__(16) char dynsm[];
    const int tid = threadIdx.x;
    const int wid = tid >> 5, lane = tid & 31;
    const int warp_m = wid & 1, warp_n = wid >> 1;
    const int m0 = blockIdx.x * 128, n0 = blockIdx.y * 128;
    const uint32_t smem_base = cvta_sh(dynsm);

    const int lr = lane >> 2, lq = lane & 3;

    float acc[4][4][4];
#pragma unroll
    for (int mi = 0; mi < 4; mi++)
#pragma unroll
        for (int ni = 0; ni < 4; ni++)
#pragma unroll
            for (int r = 0; r < 4; r++) acc[mi][ni][r] = 0.f;

    const int nk = K >> 5;

    o_load_stage(smem_base, Ah, Al, Bh, Bl, K, m0, n0, 0, 0, tid);

    for (int k0 = 0; k0 < nk; k0++) {
        if (k0 + 1 < nk) {
            o_load_stage(smem_base, Ah, Al, Bh, Bl, K, m0, n0,
                         (k0 + 1) & 1, k0 + 1, tid);
            cp_wait1();
        } else {
            cp_wait0();
        }
        __syncthreads();

        const uint32_t* sAh = (const uint32_t*)(dynsm + (size_t)(k0 & 1) * OSTG_BYTES);
        const uint32_t* sAl = sAh + PLANE_W;
        const uint32_t* sBh = sAh + 2 * PLANE_W;
        const uint32_t* sBl = sAh + 3 * PLANE_W;

#pragma unroll
        for (int ks = 0; ks < 2; ks++) {
            uint32_t ah[4][4], al[4][4], bh[4][2], bl[4][2];
#pragma unroll
            for (int mi = 0; mi < 4; mi++) {
                const int r = warp_m * 64 + mi * 16 + lr;
                const int o = r * BSTR + ks * 8 + lq;
                ah[mi][0] = sAh[o];
                ah[mi][1] = sAh[o + 8 * BSTR];
                ah[mi][2] = sAh[o + 4];
                ah[mi][3] = sAh[o + 8 * BSTR + 4];
                al[mi][0] = sAl[o];
                al[mi][1] = sAl[o + 8 * BSTR];
                al[mi][2] = sAl[o + 4];
                al[mi][3] = sAl[o + 8 * BSTR + 4];
            }
#pragma unroll
            for (int ni = 0; ni < 4; ni++) {
                const int n = warp_n * 32 + ni * 8 + lr;
                const int o = n * BSTR + ks * 8 + lq;
                bh[ni][0] = sBh[o];
                bh[ni][1] = sBh[o + 4];
                bl[ni][0] = sBl[o];
                bl[ni][1] = sBl[o + 4];
            }
#pragma unroll
            for (int mi = 0; mi < 4; mi++)
#pragma unroll
                for (int ni = 0; ni < 4; ni++) {
                    mma_bf16(acc[mi][ni], ah[mi][0], ah[mi][1], ah[mi][2], ah[mi][3],
                             bh[ni][0], bh[ni][1]);
                    mma_bf16(acc[mi][ni], ah[mi][0], ah[mi][1], ah[mi][2], ah[mi][3],
                             bl[ni][0], bl[ni][1]);
                    mma_bf16(acc[mi][ni], al[mi][0], al[mi][1], al[mi][2], al[mi][3],
                             bh[ni][0], bh[ni][1]);
                }
        }
        __syncthreads();
    }

#pragma unroll
    for (int mi = 0; mi < 4; mi++) {
        const int row0 = m0 + warp_m * 64 + mi * 16 + lr;
#pragma unroll
        for (int ni = 0; ni < 4; ni++) {
            const int col = n0 + warp_n * 32 + ni * 8 + 2 * lq;
            float* p0 = C + (size_t)row0 * N + col;
            float* p1 = p0 + 8 * N;
            *(float2*)p0 = make_float2(acc[mi][ni][0], acc[mi][ni][1]);
            *(float2*)p1 = make_float2(acc[mi][ni][2], acc[mi][ni][3]);
        }
    }
}

// ---------------------------------------------------------------------------
// Fused prep: RoPE (blocks < S_LEN) + V transpose/split (rest)
// ---------------------------------------------------------------------------
__global__ void __launch_bounds__(256) prep_fused(const float* __restrict__ freqs,
                                                  const int* __restrict__ widx) {
    __shared__ float sm[64][65];
    if (blockIdx.x < S_LEN) {
        const int l = blockIdx.x;
        const int t = threadIdx.x;
        const int dst = widx[l];
        const float* fr = freqs + (size_t)l * HD;
        float* row = g_qkv + (size_t)l * QKV_N;

        for (int p = t; p < NH * 128; p += 256) {
            const int hh = p >> 7, d = p & 127;
            const float c = fr[2 * d], s = fr[2 * d + 1];
            float* q = row + hh * HD;
            const float x1 = q[d], x2 = q[d + 128];
            q[d]       = (x1 * c - x2 * s) * QSCALE;
            q[d + 128] = (x1 * s + x2 * c) * QSCALE;
        }
        for (int p = t; p < NKV * 128; p += 256) {
            const int hh = p >> 7, d = p & 127;
            const float c = fr[2 * d], s = fr[2 * d + 1];
            const float* kk = row + NH * HD + hh * HD;
            const float x1 = kk[d], x2 = kk[d + 128];
            const float y1 = x1 * c - x2 * s;
            const float y2 = x1 * s + x2 * c;
            const size_t base = ((size_t)hh * S_LEN + dst) * HD;
            g_kh[base + d]       = hi16(y1);
            g_kh[base + d + 128] = hi16(y2);
            g_kl[base + d]       = lo16(y1);
            g_kl[base + d + 128] = lo16(y2);
        }
    } else {
        const int idx = blockIdx.x - S_LEN;
        const int j0 = (idx % 48) * 64;
        const int d0 = ((idx / 48) & 3) * 64;
        const int kvh = idx / 192;
        const int t = threadIdx.x;
#pragma unroll
        for (int i = 0; i < 16; i++) {
            const int id = t + i * 256;
            const int jr = id >> 6, dc = id & 63;
            sm[jr][dc] = g_qkv[(size_t)(j0 + jr) * QKV_N + VOFF + kvh * HD + d0 + dc];
        }
        __syncthreads();
#pragma unroll
        for (int i = 0; i < 8; i++) {
            const int id = t + i * 256;
            const int dr = id >> 5, jp = id & 31;
            const float f0 = sm[jp * 2][dr];
            const float f1 = sm[jp * 2 + 1][dr];
            const size_t go = ((size_t)kvh * HD + d0 + dr) * S_LEN + j0 + jp * 2;
            ushort2 h, l;
            h.x = hi16(f0); h.y = hi16(f1);
            l.x = lo16(f0); l.y = lo16(f1);
            *(ushort2*)(g_vh + go) = h;
            *(ushort2*)(g_vl + go) = l;
        }
    }
}

// =====================================================================
// Flash attention with FIXED-SHIFT softmax (exp(s-50); softcap bounds
// scores to [-50,50], so no running max / rescale / per-tile reduction).
// 256 threads, heavy-first ordering, 3 barriers/tile.
// =====================================================================
#define QSTR 132
#define KROW 132
#define VSTR 36
#define PSTR 36
#define N_Q (64 * QSTR)
#define N_K (64 * KROW)
#define N_V (256 * VSTR)
#define N_P (64 * PSTR)
#define ATTN_SMEM ((2 * N_Q + 2 * N_K + 2 * N_V + 2 * N_P + 512) * 4)

__global__ void __launch_bounds__(256, 1) attn_mma() {
    extern __shared__ __align__(16) char smraw[];
    uint32_t* qh32 = (uint32_t*)smraw;
    uint32_t* ql32 = qh32 + N_Q;
    uint32_t* k0s  = ql32 + N_Q;
    uint32_t* k1s  = k0s + N_K;
    uint32_t* v0s  = k1s + N_K;
    uint32_t* v1s  = v0s + N_V;
    uint32_t* ph32 = v1s + N_V;
    uint32_t* pl32 = ph32 + N_P;
    float* partsm = (float*)(pl32 + N_P);   // used once, at the end

    const uint32_t smem_base = cvta_sh(smraw);
    const uint32_t kb0 = smem_base + (2 * N_Q) * 4;
    const uint32_t kb1 = kb0 + N_K * 4;
    const uint32_t vb0 = kb1 + N_K * 4;
    const uint32_t vb1 = vb0 + N_V * 4;

    const int tid = threadIdx.x;
    const int lane = tid & 31, wid = tid >> 5;
    const int warp_m = wid & 1, warp_n = wid >> 1;
    const int lr = lane >> 2, lq = lane & 3;
    const int h = blockIdx.y, kvh = h >> 1;
    const int bx = gridDim.x - 1 - blockIdx.x;
    const int m0 = bx * 64;

    // ---- load Q once, split hi/lo ----
    {
        const int row = tid >> 2, cb = (tid & 3) * 64;
        const float* q = g_qkv + (size_t)(m0 + row) * QKV_N + h * HD + cb;
#pragma unroll
        for (int i = 0; i < 16; i++) {
            const float4 v = *(const float4*)(q + i * 4);
            const int cp = (cb + i * 4) >> 1;
            qh32[row * QSTR + cp]     = hipair(v.x, v.y);
            qh32[row * QSTR + cp + 1] = hipair(v.z, v.w);
            ql32[row * QSTR + cp]     = lopair(v.x, v.y);
            ql32[row * QSTR + cp + 1] = lopair(v.z, v.w);
        }
    }

    // running L partials (per thread, across all tiles)
    float Ls[2][2];
    Ls[0][0] = Ls[0][1] = Ls[1][0] = Ls[1][1] = 0.f;

    float oacc[2][8][4];
#pragma unroll
    for (int mf = 0; mf < 2; mf++)
#pragma unroll
        for (int nf = 0; nf < 8; nf++)
#pragma unroll
            for (int c = 0; c < 4; c++) oacc[mf][nf][c] = 0.f;

    int lo = m0 - (WIN - 1);
    if (lo < 0) lo = 0;
    const int jt0 = lo >> 6, jt1 = bx;

    // ---- prefetch first K tile ----
    {
        const int j0 = jt0 * 64;
#pragma unroll
        for (int i = 0; i < 8; i++) {
            const int u = tid + i * 256;
            const int r = u >> 5, ch = u & 31;
            const size_t go = ((size_t)kvh * S_LEN + j0 + r) * HD + ch * 8;
            const uint32_t off = (uint32_t)r * (KROW * 4) + ch * 16;
            cp16(kb0 + off, g_kh + go);
            cp16(kb1 + off, g_kl + go);
        }
        cp_commit();                       // group: K_jt0
    }

    for (int jt = jt0; jt <= jt1; jt++) {
        const int j0 = jt * 64;
        const bool haveNext = (jt < jt1);

        // ---- issue V tile (completes under QK + softmax) ----
#pragma unroll
        for (int i = 0; i < 8; i++) {
            const int u = tid + i * 256;
            const int r = u >> 3, ch = u & 7;
            const size_t go = ((size_t)kvh * HD + r) * S_LEN + j0 + ch * 8;
            const uint32_t off = (uint32_t)r * (VSTR * 4) + ch * 16;
            cp16(vb0 + off, g_vh + go);
            cp16(vb1 + off, g_vl + go);
        }
        cp_commit();                       // group: V_jt

        cp_wait1();                        // K_jt done
        __syncthreads();                   // [A] K + Q(+P/V reuse) safe

        // ---- QK^T ----
        float sacc[2][2][4];
#pragma unroll
        for (int mf = 0; mf < 2; mf++)
#pragma unroll
            for (int nf = 0; nf < 2; nf++)
#pragma unroll
                for (int c = 0; c < 4; c++) sacc[mf][nf][c] = 0.f;

#pragma unroll
        for (int ks = 0; ks < 16; ks++) {
            uint32_t ah[2][4], al[2][4];
#pragma unroll
            for (int mf = 0; mf < 2; mf++) {
                const int r = warp_m * 32 + mf * 16 + lr;
                const int o = r * QSTR + ks * 8 + lq;
                ah[mf][0] = qh32[o];
                ah[mf][1] = qh32[o + 8 * QSTR];
                ah[mf][2] = qh32[o + 4];
                ah[mf][3] = qh32[o + 8 * QSTR + 4];
                al[mf][0] = ql32[o];
                al[mf][1] = ql32[o + 8 * QSTR];
                al[mf][2] = ql32[o + 4];
                al[mf][3] = ql32[o + 8 * QSTR + 4];
            }
#pragma unroll
            for (int nf = 0; nf < 2; nf++) {
                const int n = warp_n * 16 + nf * 8 + lr;
                const int o = n * KROW + ks * 8 + lq;
                const uint32_t bh0 = k0s[o], bh1 = k0s[o + 4];
                const uint32_t bl0 = k1s[o], bl1 = k1s[o + 4];
#pragma unroll
                for (int mf = 0; mf < 2; mf++) {
                    mma_bf16(sacc[mf][nf], ah[mf][0], ah[mf][1], ah[mf][2], ah[mf][3], bh0, bh1);
                    mma_bf16(sacc[mf][nf], ah[mf][0], ah[mf][1], ah[mf][2], ah[mf][3], bl0, bl1);
                    mma_bf16(sacc[mf][nf], al[mf][0], al[mf][1], al[mf][2], al[mf][3], bh0, bh1);
                }
            }
        }

        // ---- softcap + mask + fixed-shift probs + L accumulation + P write ----
#pragma unroll
        for (int mf = 0; mf < 2; mf++) {
            const int rl0 = warp_m * 32 + mf * 16 + lr;
#pragma unroll
            for (int nf = 0; nf < 2; nf++) {
                float p[4];
#pragma unroll
                for (int c = 0; c < 4; c++) {
                    const float s = sacc[mf][nf][c];
                    const float e = __expf(s * 0.04f);
                    float val = 50.f - 100.f / (e + 1.f);
                    const int gj = j0 + warp_n * 16 + nf * 8 + lq * 2 + (c & 1);
                    const int gi = m0 + rl0 + ((c & 2) ? 8 : 0);
                    if (gj > gi || gj < gi - (WIN - 1)) val = NEGF;
                    p[c] = __expf(val - 50.f);   // scores bounded by softcap: max <= 50
                }
                Ls[mf][0] += p[0] + p[1];
                Ls[mf][1] += p[2] + p[3];
                const int cp = warp_n * 8 + nf * 4 + lq;
                ph32[rl0 * PSTR + cp]       = hipair(p[0], p[1]);
                pl32[rl0 * PSTR + cp]       = lopair(p[0], p[1]);
                ph32[(rl0 + 8) * PSTR + cp] = hipair(p[2], p[3]);
                pl32[(rl0 + 8) * PSTR + cp] = lopair(p[2], p[3]);
            }
        }

        cp_wait0();                        // V_jt done (only group in flight)
        __syncthreads();                   // [B] P + V ready; all K reads done

        // ---- prefetch next K tile (safe: barrier B fenced all K reads) ----
        if (haveNext) {
            const int jn = j0 + 64;
#pragma unroll
            for (int i = 0; i < 8; i++) {
                const int u = tid + i * 256;
                const int r = u >> 5, ch = u & 31;
                const size_t go = ((size_t)kvh * S_LEN + jn + r) * HD + ch * 8;
                const uint32_t off = (uint32_t)r * (KROW * 4) + ch * 16;
                cp16(kb0 + off, g_kh + go);
                cp16(kb1 + off, g_kl + go);
            }
            cp_commit();                   // group: K_{jt+1}
        }

        // ---- PV ----
#pragma unroll
        for (int kj = 0; kj < 4; kj++) {
            uint32_t ah[2][4], al[2][4];
#pragma unroll
            for (int mf = 0; mf < 2; mf++) {
                const int r = warp_m * 32 + mf * 16 + lr;
                const int o = r * PSTR + kj * 8 + lq;
                ah[mf][0] = ph32[o];
                ah[mf][1] = ph32[o + 8 * PSTR];
                ah[mf][2] = ph32[o + 4];
                ah[mf][3] = ph32[o + 8 * PSTR + 4];
                al[mf][0] = pl32[o];
                al[mf][1] = pl32[o + 8 * PSTR];
                al[mf][2] = pl32[o + 4];
                al[mf][3] = pl32[o + 8 * PSTR + 4];
            }
#pragma unroll
            for (int nf = 0; nf < 8; nf++) {
                const int n = warp_n * 64 + nf * 8 + lr;
                const int o = n * VSTR + kj * 8 + lq;
                const uint32_t bh0 = v0s[o], bh1 = v0s[o + 4];
                const uint32_t bl0 = v1s[o], bl1 = v1s[o + 4];
#pragma unroll
                for (int mf = 0; mf < 2; mf++) {
                    mma_bf16(oacc[mf][nf], ah[mf][0], ah[mf][1], ah[mf][2], ah[mf][3], bh0, bh1);
                    mma_bf16(oacc[mf][nf], ah[mf][0], ah[mf][1], ah[mf][2], ah[mf][3], bl0, bl1);
                    mma_bf16(oacc[mf][nf], al[mf][0], al[mf][1], al[mf][2], al[mf][3], bh0, bh1);
                }
            }
        }
        __syncthreads();                   // [C] P + V free for next tile
    }

    // ---- final L reduction (once) ----
#pragma unroll
    for (int mf = 0; mf < 2; mf++) {
        float l0 = Ls[mf][0], l1 = Ls[mf][1];
        l0 += __shfl_xor_sync(0xffffffffu, l0, 1);
        l0 += __shfl_xor_sync(0xffffffffu, l0, 2);
        l1 += __shfl_xor_sync(0xffffffffu, l1, 1);
        l1 += __shfl_xor_sync(0xffffffffu, l1, 2);
        const int rl0 = warp_m * 32 + mf * 16 + lr;
        if (lq == 0) {
            partsm[rl0 * 4 + warp_n]       = l0;
            partsm[(rl0 + 8) * 4 + warp_n] = l1;
        }
    }
    __syncthreads();

    // ---- epilogue: normalize, split to bf16 hi/lo planes ----
#pragma unroll
    for (int mf = 0; mf < 2; mf++) {
        const int rl0 = warp_m * 32 + mf * 16 + lr;
        const float L0 = partsm[rl0 * 4 + 0] + partsm[rl0 * 4 + 1] +
                         partsm[rl0 * 4 + 2] + partsm[rl0 * 4 + 3];
        const float L1 = partsm[(rl0 + 8) * 4 + 0] + partsm[(rl0 + 8) * 4 + 1] +
                         partsm[(rl0 + 8) * 4 + 2] + partsm[(rl0 + 8) * 4 + 3];
        const float i0 = 1.f / L0;
        const float i1 = 1.f / L1;
        const int r0 = m0 + rl0;
#pragma unroll
        for (int nf = 0; nf < 8; nf++) {
            const int col = warp_n * 64 + nf * 8 + lq * 2;
            const size_t ix0 = (size_t)r0 * AO_N + h * HD + col;
            const size_t ix1 = ix0 + (size_t)8 * AO_N;
            const float a0 = oacc[mf][nf][0] * i0, a1 = oacc[mf][nf][1] * i0;
            const float b0 = oacc[mf][nf][2] * i1, b1 = oacc[mf][nf][3] * i1;
            *(uint32_t*)(g_ah + ix0) = hipair(a0, a1);
            *(uint32_t*)(g_al + ix0) = lopair(a0, a1);
            *(uint32_t*)(g_ah + ix1) = hipair(b0, b1);
            *(uint32_t*)(g_al + ix1) = lopair(b0, b1);
        }
    }
}

// ---------------------------------------------------------------------------
extern "C" void kernel_launch(void* const* d_in, const int* in_sizes, int n_in,
                              void* d_out, int out_size) {
    const float* hidden = (const float*)d_in[0];
    const float* freqs  = (const float*)d_in[1];
    const int*   widx   = (const int*)d_in[2];
    const float* qkv_w  = (const float*)d_in[6];
    const float* o_w    = (const float*)d_in[7];
    float* out = (float*)d_out;

    float *qkv_ptr, *hidT_ptr, *qwT_ptr;
    uint16_t *ah_ptr, *al_ptr, *wh_ptr, *wl_ptr;
    cudaGetSymbolAddress((void**)&qkv_ptr, g_qkv);
    cudaGetSymbolAddress((void**)&hidT_ptr, g_hidT);
    cudaGetSymbolAddress((void**)&qwT_ptr, g_qwT);
    cudaGetSymbolAddress((void**)&ah_ptr, g_ah);
    cudaGetSymbolAddress((void**)&al_ptr, g_al);
    cudaGetSymbolAddress((void**)&wh_ptr, g_wh);
    cudaGetSymbolAddress((void**)&wl_ptr, g_wl);

    cudaFuncSetAttribute(attn_mma,
                         cudaFuncAttributeMaxDynamicSharedMemorySize, ATTN_SMEM);
    cudaFuncSetAttribute(gemm_mma,
                         cudaFuncAttributeMaxDynamicSharedMemorySize, GEMM_SMEM);
    cudaFuncSetAttribute(gemm_bf3,
                         cudaFuncAttributeMaxDynamicSharedMemorySize, OGEMM_SMEM);

    // attn_mma stays launch #4 (ncu capture slot)
    cvt_tf32_both<<<2048, 256>>>(hidden, hidT_ptr, S_LEN * HID / 4,
                                 qkv_w, qwT_ptr, QKV_N * HID / 4);
    gemm_mma<<<dim3(S_LEN / 128, QKV_N / 128), 256, GEMM_SMEM>>>(
        hidT_ptr, qwT_ptr, qkv_ptr, S_LEN, QKV_N, HID);
    prep_fused<<<S_LEN + 1536, 256>>>(freqs, widx);
    attn_mma<<<dim3(S_LEN / 64, NH), 256, ATTN_SMEM>>>();
    split_planes<<<1024, 256>>>(o_w, wh_ptr, wl_ptr, HID * AO_N / 4);
    gemm_bf3<<<dim3(S_LEN / 128, HID / 128), 256, OGEMM_SMEM>>>(
        ah_ptr, al_ptr, wh_ptr, wl_ptr, out, S_LEN, HID, AO_N);
}

// round 16
// speedup vs baseline: 1.0929x; 1.0049x over previous
#include <cuda_runtime.h>
#include <cstdint>
#include <math.h>

#define S_LEN 3072
#define HID 3584
#define NH 16
#define NKV 8
#define HD 256
#define WIN 2048
#define QKV_N 8192
#define NEGF -2.3819763e38f
#define QSCALE 0.0625f
#define AO_N 4096
#define VOFF (NH * HD + NKV * HD)

typedef unsigned long long u64;

// ---------------- bf16 split helpers ----------------
__device__ __forceinline__ float hif(float a) {
    return __uint_as_float(__float_as_uint(a) & 0xFFFF0000u);
}
__device__ __forceinline__ uint32_t hipair(float a, float b) {
    uint32_t r;
    asm("prmt.b32 %0, %1, %2, 0x7632;"
        : "=r"(r) : "r"(__float_as_uint(a)), "r"(__float_as_uint(b)));
    return r;
}
__device__ __forceinline__ uint32_t lopair(float a, float b) {
    uint32_t r;
    asm("cvt.rn.bf16x2.f32 %0, %1, %2;"
        : "=r"(r) : "f"(b - hif(b)), "f"(a - hif(a)));
    return r;
}
__device__ __forceinline__ uint16_t hi16(float a) {
    return (uint16_t)(__float_as_uint(a) >> 16);
}
__device__ __forceinline__ uint16_t lo16(float a) {
    uint16_t u;
    asm("cvt.rn.bf16.f32 %0, %1;" : "=h"(u) : "f"(a - hif(a)));
    return u;
}

__device__ __forceinline__ void mma_bf16(float* c, uint32_t a0, uint32_t a1,
                                         uint32_t a2, uint32_t a3,
                                         uint32_t b0, uint32_t b1) {
    asm volatile(
        "mma.sync.aligned.m16n8k16.row.col.f32.bf16.bf16.f32 "
        "{%0,%1,%2,%3}, {%4,%5,%6,%7}, {%8,%9}, {%0,%1,%2,%3};"
        : "+f"(c[0]), "+f"(c[1]), "+f"(c[2]), "+f"(c[3])
        : "r"(a0), "r"(a1), "r"(a2), "r"(a3), "r"(b0), "r"(b1));
}

// ---------------- scratch ----------------
__device__ float g_qkv[S_LEN * QKV_N];
__device__ float g_hidT[S_LEN * HID];
__device__ float g_qwT[QKV_N * HID];
__device__ uint16_t g_kh[NKV * S_LEN * HD];
__device__ uint16_t g_kl[NKV * S_LEN * HD];
__device__ uint16_t g_vh[NKV * HD * S_LEN];
__device__ uint16_t g_vl[NKV * HD * S_LEN];
__device__ uint16_t g_ah[S_LEN * AO_N];
__device__ uint16_t g_al[S_LEN * AO_N];
__device__ uint16_t g_wh[HID * AO_N];
__device__ uint16_t g_wl[HID * AO_N];

// ---------------- common asm helpers ----------------
__device__ __forceinline__ uint32_t cvta_sh(const void* p) {
    uint32_t a;
    asm("{ .reg .u64 t; cvta.to.shared.u64 t, %1; cvt.u32.u64 %0, t; }"
        : "=r"(a) : "l"(p));
    return a;
}
__device__ __forceinline__ void cp16(uint32_t dst, const void* src) {
    asm volatile("cp.async.cg.shared.global [%0], [%1], 16;"
                 :: "r"(dst), "l"(src));
}
__device__ __forceinline__ void cp_commit() {
    asm volatile("cp.async.commit_group;" ::: "memory");
}
__device__ __forceinline__ void cp_wait1() {
    asm volatile("cp.async.wait_group 1;" ::: "memory");
}
__device__ __forceinline__ void cp_wait0() {
    asm volatile("cp.async.wait_group 0;" ::: "memory");
}
__device__ __forceinline__ uint32_t f2tf32(float x) {
    uint32_t r;
    asm("cvt.rna.tf32.f32 %0, %1;" : "=r"(r) : "f"(x));
    return r;
}
__device__ __forceinline__ void mma_tf32(float* c, const uint32_t* a,
                                         const uint32_t* b) {
    asm volatile(
        "mma.sync.aligned.m16n8k8.row.col.f32.tf32.tf32.f32 "
        "{%0,%1,%2,%3}, {%4,%5,%6,%7}, {%8,%9}, {%0,%1,%2,%3};"
        : "+f"(c[0]), "+f"(c[1]), "+f"(c[2]), "+f"(c[3])
        : "r"(a[0]), "r"(a[1]), "r"(a[2]), "r"(a[3]), "r"(b[0]), "r"(b[1]));
}

// =====================================================================
// fused pre-round fp32 -> tf32 for BOTH hidden and qkv_w
// =====================================================================
__global__ void __launch_bounds__(256) cvt_tf32_both(const float* __restrict__ s1,
                                                     float* __restrict__ d1, int n1,
                                                     const float* __restrict__ s2,
                                                     float* __restrict__ d2, int n2) {
    const int total = n1 + n2;
    for (int i = blockIdx.x * blockDim.x + threadIdx.x; i < total;
         i += gridDim.x * blockDim.x) {
        const float4* sp;
        float4* dp;
        int j;
        if (i < n1) { sp = (const float4*)s1; dp = (float4*)d1; j = i; }
        else        { sp = (const float4*)s2; dp = (float4*)d2; j = i - n1; }
        const float4 v = sp[j];
        float4 o;
        o.x = __uint_as_float(f2tf32(v.x));
        o.y = __uint_as_float(f2tf32(v.y));
        o.z = __uint_as_float(f2tf32(v.z));
        o.w = __uint_as_float(f2tf32(v.w));
        dp[j] = o;
    }
}

// =====================================================================
// tf32 mma.sync GEMM for QKV projection — 2 CTAs/SM
// =====================================================================
#define GSTAGE 3
#define SROW 36
#define STAGE_FLOATS (128 * SROW)
#define STAGE_BYTES  (STAGE_FLOATS * 4 * 2)
#define GEMM_SMEM (GSTAGE * STAGE_BYTES)

__device__ __forceinline__ void g_load_stage(uint32_t smem_base,
                                             const float* __restrict__ A,
                                             const float* __restrict__ B,
                                             int K, int m0, int n0,
                                             int stage, int chunk, int tid) {
    const uint32_t sa = smem_base + stage * STAGE_BYTES;
    const uint32_t sb = sa + STAGE_FLOATS * 4;
    const float* Ab = A + (size_t)m0 * K + chunk * 32;
    const float* Bb = B + (size_t)n0 * K + chunk * 32;
#pragma unroll
    for (int i = 0; i < 4; i++) {
        const int u = tid + i * 256;
        const int r = u >> 3, ch = u & 7;
        const uint32_t off = (uint32_t)r * (SROW * 4) + ch * 16;
        cp16(sa + off, Ab + (size_t)r * K + ch * 4);
        cp16(sb + off, Bb + (size_t)r * K + ch * 4);
    }
    cp_commit();
}

__global__ void __launch_bounds__(256, 2) gemm_mma(const float* __restrict__ A,
                                                   const float* __restrict__ B,
                                                   float* __restrict__ C,
                                                   int M, int N, int K) {
    extern __shared__ __align__(16) char dynsm[];
    const int tid = threadIdx.x;
    const int wid = tid >> 5, lane = tid & 31;
    const int warp_m = wid & 1, warp_n = wid >> 1;
    const int m0 = blockIdx.x * 128, n0 = blockIdx.y * 128;
    const uint32_t smem_base = cvta_sh(dynsm);

    const int lr = lane >> 2;
    const int lc = lane & 3;

    float acc[4][4][4];
#pragma unroll
    for (int mi = 0; mi < 4; mi++)
#pragma unroll
        for (int ni = 0; ni < 4; ni++)
#pragma unroll
            for (int r = 0; r < 4; r++) acc[mi][ni][r] = 0.f;

    const int nk = K >> 5;

    g_load_stage(smem_base, A, B, K, m0, n0, 0, 0, tid);
    g_load_stage(smem_base, A, B, K, m0, n0, 1, 1, tid);

    for (int k0 = 0; k0 < nk; k0++) {
        cp_wait1();
        __syncthreads();
        if (k0 + 2 < nk)
            g_load_stage(smem_base, A, B, K, m0, n0, (k0 + 2) % GSTAGE,
                         k0 + 2, tid);

        const uint32_t* sA = (const uint32_t*)(dynsm + (size_t)(k0 % GSTAGE) * STAGE_BYTES);
        const uint32_t* sB = sA + STAGE_FLOATS;

#pragma unroll
        for (int ks = 0; ks < 4; ks++) {
            uint32_t af[4][4], bf[4][2];
#pragma unroll
            for (int mi = 0; mi < 4; mi++) {
                const int r = warp_m * 64 + mi * 16 + lr;
                const int c = ks * 8 + lc;
                af[mi][0] = sA[r * SROW + c];
                af[mi][1] = sA[(r + 8) * SROW + c];
                af[mi][2] = sA[r * SROW + c + 4];
                af[mi][3] = sA[(r + 8) * SROW + c + 4];
            }
#pragma unroll
            for (int ni = 0; ni < 4; ni++) {
                const int n = warp_n * 32 + ni * 8 + lr;
                const int c = ks * 8 + lc;
                bf[ni][0] = sB[n * SROW + c];
                bf[ni][1] = sB[n * SROW + c + 4];
            }
#pragma unroll
            for (int mi = 0; mi < 4; mi++)
#pragma unroll
                for (int ni = 0; ni < 4; ni++)
                    mma_tf32(acc[mi][ni], af[mi], bf[ni]);
        }
    }

#pragma unroll
    for (int mi = 0; mi < 4; mi++) {
        const int row0 = m0 + warp_m * 64 + mi * 16 + lr;
#pragma unroll
        for (int ni = 0; ni < 4; ni++) {
            const int col = n0 + warp_n * 32 + ni * 8 + 2 * lc;
            float* p0 = C + (size_t)row0 * N + col;
            float* p1 = p0 + 8 * N;
            *(float2*)p0 = make_float2(acc[mi][ni][0], acc[mi][ni][1]);
            *(float2*)p1 = make_float2(acc[mi][ni][2], acc[mi][ni][3]);
        }
    }
}

// =====================================================================
// split fp32 -> bf16 hi/lo planes (o_w only)
// =====================================================================
__global__ void __launch_bounds__(256) split_planes(const float* __restrict__ src,
                                                    uint16_t* __restrict__ hi,
                                                    uint16_t* __restrict__ lo,
                                                    int n4) {
    for (int i = blockIdx.x * blockDim.x + threadIdx.x; i < n4;
         i += gridDim.x * blockDim.x) {
        const float4 v = ((const float4*)src)[i];
        ushort4 h, l;
        h.x = hi16(v.x); h.y = hi16(v.y); h.z = hi16(v.z); h.w = hi16(v.w);
        l.x = lo16(v.x); l.y = lo16(v.y); l.z = lo16(v.z); l.w = lo16(v.w);
        ((ushort4*)hi)[i] = h;
        ((ushort4*)lo)[i] = l;
    }
}

// =====================================================================
// bf16x3 split GEMM for O-projection — 2-stage, 2 CTAs/SM,
// pass-outer mma order (same-acc distance 16, bit-identical sums)
// =====================================================================
#define OSTAGE 2
#define BSTR 20
#define PLANE_W (128 * BSTR)
#define OSTG_BYTES (4 * PLANE_W * 4)
#define OGEMM_SMEM (OSTAGE * OSTG_BYTES)

__device__ __forceinline__ void o_load_stage(uint32_t smem_base,
                                             const uint16_t* __restrict__ Ah,
                                             const uint16_t* __restrict__ Al,
                                             const uint16_t* __restrict__ Bh,
                                             const uint16_t* __restrict__ Bl,
                                             int K, int m0, int n0,
                                             int stage, int chunk, int tid) {
    const uint32_t s0 = smem_base + stage * OSTG_BYTES;
    const uint16_t* p0 = Ah + (size_t)m0 * K + chunk * 32;
    const uint16_t* p1 = Al + (size_t)m0 * K + chunk * 32;
    const uint16_t* p2 = Bh + (size_t)n0 * K + chunk * 32;
    const uint16_t* p3 = Bl + (size_t)n0 * K + chunk * 32;
#pragma unroll
    for (int i = 0; i < 2; i++) {
        const int u = tid + i * 256;
        const int r = u >> 2, ch = u & 3;
        const uint32_t off = (uint32_t)r * (BSTR * 4) + ch * 16;
        const size_t go = (size_t)r * K + ch * 8;
        cp16(s0 + 0 * PLANE_W * 4 + off, p0 + go);
        cp16(s0 + 1 * PLANE_W * 4 + off, p1 + go);
        cp16(s0 + 2 * PLANE_W * 4 + off, p2 + go);
        cp16(s0 + 3 * PLANE_W * 4 + off, p3 + go);
    }
    cp_commit();
}

__global__ void __launch_bounds__(256, 2) gemm_bf3(const uint16_t* __restrict__ Ah,
                                                   const uint16_t* __restrict__ Al,
                                                   const uint16_t* __restrict__ Bh,
                                                   const uint16_t* __restrict__ Bl,
                                                   float* __restrict__ C,
                                                   int M, int N, int K) {
    extern __shared__ __align__(16) char dynsm[];
    const int tid = threadIdx.x;
    const int wid = tid >> 5, lane = tid & 31;
    const int warp_m = wid & 1, warp_n = wid >> 1;
    const int m0 = blockIdx.x * 128, n0 = blockIdx.y * 128;
    const uint32_t smem_base = cvta_sh(dynsm);

    const int lr = lane >> 2, lq = lane & 3;

    float acc[4][4][4];
#pragma unroll
    for (int mi = 0; mi < 4; mi++)
#pragma unroll
        for (int ni = 0; ni < 4; ni++)
#pragma unroll
            for (int r = 0; r < 4; r++) acc[mi][ni][r] = 0.f;

    const int nk = K >> 5;

    o_load_stage(smem_base, Ah, Al, Bh, Bl, K, m0, n0, 0, 0, tid);

    for (int k0 = 0; k0 < nk; k0++) {
        if (k0 + 1 < nk) {
            o_load_stage(smem_base, Ah, Al, Bh, Bl, K, m0, n0,
                         (k0 + 1) & 1, k0 + 1, tid);
            cp_wait1();
        } else {
            cp_wait0();
        }
        __syncthreads();

        const uint32_t* sAh = (const uint32_t*)(dynsm + (size_t)(k0 & 1) * OSTG_BYTES);
        const uint32_t* sAl = sAh + PLANE_W;
        const uint32_t* sBh = sAh + 2 * PLANE_W;
        const uint32_t* sBl = sAh + 3 * PLANE_W;

#pragma unroll
        for (int ks = 0; ks < 2; ks++) {
            uint32_t ah[4][4], al[4][4], bh[4][2], bl[4][2];
#pragma unroll
            for (int mi = 0; mi < 4; mi++) {
                const int r = warp_m * 64 + mi * 16 + lr;
                const int o = r * BSTR + ks * 8 + lq;
                ah[mi][0] = sAh[o];
                ah[mi][1] = sAh[o + 8 * BSTR];
                ah[mi][2] = sAh[o + 4];
                ah[mi][3] = sAh[o + 8 * BSTR + 4];
                al[mi][0] = sAl[o];
                al[mi][1] = sAl[o + 8 * BSTR];
                al[mi][2] = sAl[o + 4];
                al[mi][3] = sAl[o + 8 * BSTR + 4];
            }
#pragma unroll
            for (int ni = 0; ni < 4; ni++) {
                const int n = warp_n * 32 + ni * 8 + lr;
                const int o = n * BSTR + ks * 8 + lq;
                bh[ni][0] = sBh[o];
                bh[ni][1] = sBh[o + 4];
                bl[ni][0] = sBl[o];
                bl[ni][1] = sBl[o + 4];
            }
            // pass-outer: per-acc order stays hh, hl, lh (bit-identical)
#pragma unroll
            for (int mi = 0; mi < 4; mi++)
#pragma unroll
                for (int ni = 0; ni < 4; ni++)
                    mma_bf16(acc[mi][ni], ah[mi][0], ah[mi][1], ah[mi][2], ah[mi][3],
                             bh[ni][0], bh[ni][1]);
#pragma unroll
            for (int mi = 0; mi < 4; mi++)
#pragma unroll
                for (int ni = 0; ni < 4; ni++)
                    mma_bf16(acc[mi][ni], ah[mi][0], ah[mi][1], ah[mi][2], ah[mi][3],
                             bl[ni][0], bl[ni][1]);
#pragma unroll
            for (int mi = 0; mi < 4; mi++)
#pragma unroll
                for (int ni = 0; ni < 4; ni++)
                    mma_bf16(acc[mi][ni], al[mi][0], al[mi][1], al[mi][2], al[mi][3],
                             bh[ni][0], bh[ni][1]);
        }
        __syncthreads();
    }

#pragma unroll
    for (int mi = 0; mi < 4; mi++) {
        const int row0 = m0 + warp_m * 64 + mi * 16 + lr;
#pragma unroll
        for (int ni = 0; ni < 4; ni++) {
            const int col = n0 + warp_n * 32 + ni * 8 + 2 * lq;
            float* p0 = C + (size_t)row0 * N + col;
            float* p1 = p0 + 8 * N;
            *(float2*)p0 = make_float2(acc[mi][ni][0], acc[mi][ni][1]);
            *(float2*)p1 = make_float2(acc[mi][ni][2], acc[mi][ni][3]);
        }
    }
}

// ---------------------------------------------------------------------------
// Fused prep: RoPE (blocks < S_LEN) + V transpose/split (rest)
// ---------------------------------------------------------------------------
__global__ void __launch_bounds__(256) prep_fused(const float* __restrict__ freqs,
                                                  const int* __restrict__ widx) {
    __shared__ float sm[64][65];
    if (blockIdx.x < S_LEN) {
        const int l = blockIdx.x;
        const int t = threadIdx.x;
        const int dst = widx[l];
        const float* fr = freqs + (size_t)l * HD;
        float* row = g_qkv + (size_t)l * QKV_N;

        for (int p = t; p < NH * 128; p += 256) {
            const int hh = p >> 7, d = p & 127;
            const float c = fr[2 * d], s = fr[2 * d + 1];
            float* q = row + hh * HD;
            const float x1 = q[d], x2 = q[d + 128];
            q[d]       = (x1 * c - x2 * s) * QSCALE;
            q[d + 128] = (x1 * s + x2 * c) * QSCALE;
        }
        for (int p = t; p < NKV * 128; p += 256) {
            const int hh = p >> 7, d = p & 127;
            const float c = fr[2 * d], s = fr[2 * d + 1];
            const float* kk = row + NH * HD + hh * HD;
            const float x1 = kk[d], x2 = kk[d + 128];
            const float y1 = x1 * c - x2 * s;
            const float y2 = x1 * s + x2 * c;
            const size_t base = ((size_t)hh * S_LEN + dst) * HD;
            g_kh[base + d]       = hi16(y1);
            g_kh[base + d + 128] = hi16(y2);
            g_kl[base + d]       = lo16(y1);
            g_kl[base + d + 128] = lo16(y2);
        }
    } else {
        const int idx = blockIdx.x - S_LEN;
        const int j0 = (idx % 48) * 64;
        const int d0 = ((idx / 48) & 3) * 64;
        const int kvh = idx / 192;
        const int t = threadIdx.x;
#pragma unroll
        for (int i = 0; i < 16; i++) {
            const int id = t + i * 256;
            const int jr = id >> 6, dc = id & 63;
            sm[jr][dc] = g_qkv[(size_t)(j0 + jr) * QKV_N + VOFF + kvh * HD + d0 + dc];
        }
        __syncthreads();
#pragma unroll
        for (int i = 0; i < 8; i++) {
            const int id = t + i * 256;
            const int dr = id >> 5, jp = id & 31;
            const float f0 = sm[jp * 2][dr];
            const float f1 = sm[jp * 2 + 1][dr];
            const size_t go = ((size_t)kvh * HD + d0 + dr) * S_LEN + j0 + jp * 2;
            ushort2 h, l;
            h.x = hi16(f0); h.y = hi16(f1);
            l.x = lo16(f0); l.y = lo16(f1);
            *(ushort2*)(g_vh + go) = h;
            *(ushort2*)(g_vl + go) = l;
        }
    }
}

// =====================================================================
// Flash attention: fixed-shift softmax, pass-outer mma order.
// 256 threads, heavy-first ordering, 3 barriers/tile.
// =====================================================================
#define QSTR 132
#define KROW 132
#define VSTR 36
#define PSTR 36
#define N_Q (64 * QSTR)
#define N_K (64 * KROW)
#define N_V (256 * VSTR)
#define N_P (64 * PSTR)
#define ATTN_SMEM ((2 * N_Q + 2 * N_K + 2 * N_V + 2 * N_P + 512) * 4)

__global__ void __launch_bounds__(256, 1) attn_mma() {
    extern __shared__ __align__(16) char smraw[];
    uint32_t* qh32 = (uint32_t*)smraw;
    uint32_t* ql32 = qh32 + N_Q;
    uint32_t* k0s  = ql32 + N_Q;
    uint32_t* k1s  = k0s + N_K;
    uint32_t* v0s  = k1s + N_K;
    uint32_t* v1s  = v0s + N_V;
    uint32_t* ph32 = v1s + N_V;
    uint32_t* pl32 = ph32 + N_P;
    float* partsm = (float*)(pl32 + N_P);

    const uint32_t smem_base = cvta_sh(smraw);
    const uint32_t kb0 = smem_base + (2 * N_Q) * 4;
    const uint32_t kb1 = kb0 + N_K * 4;
    const uint32_t vb0 = kb1 + N_K * 4;
    const uint32_t vb1 = vb0 + N_V * 4;

    const int tid = threadIdx.x;
    const int lane = tid & 31, wid = tid >> 5;
    const int warp_m = wid & 1, warp_n = wid >> 1;
    const int lr = lane >> 2, lq = lane & 3;
    const int h = blockIdx.y, kvh = h >> 1;
    const int bx = gridDim.x - 1 - blockIdx.x;
    const int m0 = bx * 64;

    // ---- load Q once, split hi/lo ----
    {
        const int row = tid >> 2, cb = (tid & 3) * 64;
        const float* q = g_qkv + (size_t)(m0 + row) * QKV_N + h * HD + cb;
#pragma unroll
        for (int i = 0; i < 16; i++) {
            const float4 v = *(const float4*)(q + i * 4);
            const int cp = (cb + i * 4) >> 1;
            qh32[row * QSTR + cp]     = hipair(v.x, v.y);
            qh32[row * QSTR + cp + 1] = hipair(v.z, v.w);
            ql32[row * QSTR + cp]     = lopair(v.x, v.y);
            ql32[row * QSTR + cp + 1] = lopair(v.z, v.w);
        }
    }

    float Ls[2][2];
    Ls[0][0] = Ls[0][1] = Ls[1][0] = Ls[1][1] = 0.f;

    float oacc[2][8][4];
#pragma unroll
    for (int mf = 0; mf < 2; mf++)
#pragma unroll
        for (int nf = 0; nf < 8; nf++)
#pragma unroll
            for (int c = 0; c < 4; c++) oacc[mf][nf][c] = 0.f;

    int lo = m0 - (WIN - 1);
    if (lo < 0) lo = 0;
    const int jt0 = lo >> 6, jt1 = bx;

    // ---- prefetch first K tile ----
    {
        const int j0 = jt0 * 64;
#pragma unroll
        for (int i = 0; i < 8; i++) {
            const int u = tid + i * 256;
            const int r = u >> 5, ch = u & 31;
            const size_t go = ((size_t)kvh * S_LEN + j0 + r) * HD + ch * 8;
            const uint32_t off = (uint32_t)r * (KROW * 4) + ch * 16;
            cp16(kb0 + off, g_kh + go);
            cp16(kb1 + off, g_kl + go);
        }
        cp_commit();
    }

    for (int jt = jt0; jt <= jt1; jt++) {
        const int j0 = jt * 64;
        const bool haveNext = (jt < jt1);

        // ---- issue V tile ----
#pragma unroll
        for (int i = 0; i < 8; i++) {
            const int u = tid + i * 256;
            const int r = u >> 3, ch = u & 7;
            const size_t go = ((size_t)kvh * HD + r) * S_LEN + j0 + ch * 8;
            const uint32_t off = (uint32_t)r * (VSTR * 4) + ch * 16;
            cp16(vb0 + off, g_vh + go);
            cp16(vb1 + off, g_vl + go);
        }
        cp_commit();

        cp_wait1();
        __syncthreads();                   // [A]

        // ---- QK^T (pass-outer per ks; per-acc order hh,hl,lh preserved) ----
        float sacc[2][2][4];
#pragma unroll
        for (int mf = 0; mf < 2; mf++)
#pragma unroll
            for (int nf = 0; nf < 2; nf++)
#pragma unroll
                for (int c = 0; c < 4; c++) sacc[mf][nf][c] = 0.f;

#pragma unroll
        for (int ks = 0; ks < 16; ks++) {
            uint32_t ah[2][4], al[2][4], bh[2][2], bl[2][2];
#pragma unroll
            for (int mf = 0; mf < 2; mf++) {
                const int r = warp_m * 32 + mf * 16 + lr;
                const int o = r * QSTR + ks * 8 + lq;
                ah[mf][0] = qh32[o];
                ah[mf][1] = qh32[o + 8 * QSTR];
                ah[mf][2] = qh32[o + 4];
                ah[mf][3] = qh32[o + 8 * QSTR + 4];
                al[mf][0] = ql32[o];
                al[mf][1] = ql32[o + 8 * QSTR];
                al[mf][2] = ql32[o + 4];
                al[mf][3] = ql32[o + 8 * QSTR + 4];
            }
#pragma unroll
            for (int nf = 0; nf < 2; nf++) {
                const int n = warp_n * 16 + nf * 8 + lr;
                const int o = n * KROW + ks * 8 + lq;
                bh[nf][0] = k0s[o]; bh[nf][1] = k0s[o + 4];
                bl[nf][0] = k1s[o]; bl[nf][1] = k1s[o + 4];
            }
#pragma unroll
            for (int nf = 0; nf < 2; nf++)
#pragma unroll
                for (int mf = 0; mf < 2; mf++)
                    mma_bf16(sacc[mf][nf], ah[mf][0], ah[mf][1], ah[mf][2], ah[mf][3],
                             bh[nf][0], bh[nf][1]);
#pragma unroll
            for (int nf = 0; nf < 2; nf++)
#pragma unroll
                for (int mf = 0; mf < 2; mf++)
                    mma_bf16(sacc[mf][nf], ah[mf][0], ah[mf][1], ah[mf][2], ah[mf][3],
                             bl[nf][0], bl[nf][1]);
#pragma unroll
            for (int nf = 0; nf < 2; nf++)
#pragma unroll
                for (int mf = 0; mf < 2; mf++)
                    mma_bf16(sacc[mf][nf], al[mf][0], al[mf][1], al[mf][2], al[mf][3],
                             bh[nf][0], bh[nf][1]);
        }

        // ---- softcap + mask + fixed-shift probs + L accumulation + P write ----
#pragma unroll
        for (int mf = 0; mf < 2; mf++) {
            const int rl0 = warp_m * 32 + mf * 16 + lr;
#pragma unroll
            for (int nf = 0; nf < 2; nf++) {
                float p[4];
#pragma unroll
                for (int c = 0; c < 4; c++) {
                    const float s = sacc[mf][nf][c];
                    const float e = __expf(s * 0.04f);
                    float val = 50.f - 100.f / (e + 1.f);
                    const int gj = j0 + warp_n * 16 + nf * 8 + lq * 2 + (c & 1);
                    const int gi = m0 + rl0 + ((c & 2) ? 8 : 0);
                    if (gj > gi || gj < gi - (WIN - 1)) val = NEGF;
                    p[c] = __expf(val - 50.f);
                }
                Ls[mf][0] += p[0] + p[1];
                Ls[mf][1] += p[2] + p[3];
                const int cp = warp_n * 8 + nf * 4 + lq;
                ph32[rl0 * PSTR + cp]       = hipair(p[0], p[1]);
                pl32[rl0 * PSTR + cp]       = lopair(p[0], p[1]);
                ph32[(rl0 + 8) * PSTR + cp] = hipair(p[2], p[3]);
                pl32[(rl0 + 8) * PSTR + cp] = lopair(p[2], p[3]);
            }
        }

        cp_wait0();
        __syncthreads();                   // [B]

        // ---- prefetch next K tile ----
        if (haveNext) {
            const int jn = j0 + 64;
#pragma unroll
            for (int i = 0; i < 8; i++) {
                const int u = tid + i * 256;
                const int r = u >> 5, ch = u & 31;
                const size_t go = ((size_t)kvh * S_LEN + jn + r) * HD + ch * 8;
                const uint32_t off = (uint32_t)r * (KROW * 4) + ch * 16;
                cp16(kb0 + off, g_kh + go);
                cp16(kb1 + off, g_kl + go);
            }
            cp_commit();
        }

        // ---- PV (pass-outer per kj; all V fragments resident) ----
#pragma unroll
        for (int kj = 0; kj < 4; kj++) {
            uint32_t ah[2][4], al[2][4], vh[8][2], vl[8][2];
#pragma unroll
            for (int mf = 0; mf < 2; mf++) {
                const int r = warp_m * 32 + mf * 16 + lr;
                const int o = r * PSTR + kj * 8 + lq;
                ah[mf][0] = ph32[o];
                ah[mf][1] = ph32[o + 8 * PSTR];
                ah[mf][2] = ph32[o + 4];
                ah[mf][3] = ph32[o + 8 * PSTR + 4];
                al[mf][0] = pl32[o];
                al[mf][1] = pl32[o + 8 * PSTR];
                al[mf][2] = pl32[o + 4];
                al[mf][3] = pl32[o + 8 * PSTR + 4];
            }
#pragma unroll
            for (int nf = 0; nf < 8; nf++) {
                const int n = warp_n * 64 + nf * 8 + lr;
                const int o = n * VSTR + kj * 8 + lq;
                vh[nf][0] = v0s[o]; vh[nf][1] = v0s[o + 4];
                vl[nf][0] = v1s[o]; vl[nf][1] = v1s[o + 4];
            }
#pragma unroll
            for (int nf = 0; nf < 8; nf++)
#pragma unroll
                for (int mf = 0; mf < 2; mf++)
                    mma_bf16(oacc[mf][nf], ah[mf][0], ah[mf][1], ah[mf][2], ah[mf][3],
                             vh[nf][0], vh[nf][1]);
#pragma unroll
            for (int nf = 0; nf < 8; nf++)
#pragma unroll
                for (int mf = 0; mf < 2; mf++)
                    mma_bf16(oacc[mf][nf], ah[mf][0], ah[mf][1], ah[mf][2], ah[mf][3],
                             vl[nf][0], vl[nf][1]);
#pragma unroll
            for (int nf = 0; nf < 8; nf++)
#pragma unroll
                for (int mf = 0; mf < 2; mf++)
                    mma_bf16(oacc[mf][nf], al[mf][0], al[mf][1], al[mf][2], al[mf][3],
                             vh[nf][0], vh[nf][1]);
        }
        __syncthreads();                   // [C]
    }

    // ---- final L reduction ----
#pragma unroll
    for (int mf = 0; mf < 2; mf++) {
        float l0 = Ls[mf][0], l1 = Ls[mf][1];
        l0 += __shfl_xor_sync(0xffffffffu, l0, 1);
        l0 += __shfl_xor_sync(0xffffffffu, l0, 2);
        l1 += __shfl_xor_sync(0xffffffffu, l1, 1);
        l1 += __shfl_xor_sync(0xffffffffu, l1, 2);
        const int rl0 = warp_m * 32 + mf * 16 + lr;
        if (lq == 0) {
            partsm[rl0 * 4 + warp_n]       = l0;
            partsm[(rl0 + 8) * 4 + warp_n] = l1;
        }
    }
    __syncthreads();

    // ---- epilogue ----
#pragma unroll
    for (int mf = 0; mf < 2; mf++) {
        const int rl0 = warp_m * 32 + mf * 16 + lr;
        const float L0 = partsm[rl0 * 4 + 0] + partsm[rl0 * 4 + 1] +
                         partsm[rl0 * 4 + 2] + partsm[rl0 * 4 + 3];
        const float L1 = partsm[(rl0 + 8) * 4 + 0] + partsm[(rl0 + 8) * 4 + 1] +
                         partsm[(rl0 + 8) * 4 + 2] + partsm[(rl0 + 8) * 4 + 3];
        const float i0 = 1.f / L0;
        const float i1 = 1.f / L1;
        const int r0 = m0 + rl0;
#pragma unroll
        for (int nf = 0; nf < 8; nf++) {
            const int col = warp_n * 64 + nf * 8 + lq * 2;
            const size_t ix0 = (size_t)r0 * AO_N + h * HD + col;
            const size_t ix1 = ix0 + (size_t)8 * AO_N;
            const float a0 = oacc[mf][nf][0] * i0, a1 = oacc[mf][nf][1] * i0;
            const float b0 = oacc[mf][nf][2] * i1, b1 = oacc[mf][nf][3] * i1;
            *(uint32_t*)(g_ah + ix0) = hipair(a0, a1);
            *(uint32_t*)(g_al + ix0) = lopair(a0, a1);
            *(uint32_t*)(g_ah + ix1) = hipair(b0, b1);
            *(uint32_t*)(g_al + ix1) = lopair(b0, b1);
        }
    }
}

// ---------------------------------------------------------------------------
extern "C" void kernel_launch(void* const* d_in, const int* in_sizes, int n_in,
                              void* d_out, int out_size) {
    const float* hidden = (const float*)d_in[0];
    const float* freqs  = (const float*)d_in[1];
    const int*   widx   = (const int*)d_in[2];
    const float* qkv_w  = (const float*)d_in[6];
    const float* o_w    = (const float*)d_in[7];
    float* out = (float*)d_out;

    float *qkv_ptr, *hidT_ptr, *qwT_ptr;
    uint16_t *ah_ptr, *al_ptr, *wh_ptr, *wl_ptr;
    cudaGetSymbolAddress((void**)&qkv_ptr, g_qkv);
    cudaGetSymbolAddress((void**)&hidT_ptr, g_hidT);
    cudaGetSymbolAddress((void**)&qwT_ptr, g_qwT);
    cudaGetSymbolAddress((void**)&ah_ptr, g_ah);
    cudaGetSymbolAddress((void**)&al_ptr, g_al);
    cudaGetSymbolAddress((void**)&wh_ptr, g_wh);
    cudaGetSymbolAddress((void**)&wl_ptr, g_wl);

    cudaFuncSetAttribute(attn_mma,
                         cudaFuncAttributeMaxDynamicSharedMemorySize, ATTN_SMEM);
    cudaFuncSetAttribute(gemm_mma,
                         cudaFuncAttributeMaxDynamicSharedMemorySize, GEMM_SMEM);
    cudaFuncSetAttribute(gemm_bf3,
                         cudaFuncAttributeMaxDynamicSharedMemorySize, OGEMM_SMEM);

    // attn_mma stays launch #4 (ncu capture slot)
    cvt_tf32_both<<<2048, 256>>>(hidden, hidT_ptr, S_LEN * HID / 4,
                                 qkv_w, qwT_ptr, QKV_N * HID / 4);
    gemm_mma<<<dim3(S_LEN / 128, QKV_N / 128), 256, GEMM_SMEM>>>(
        hidT_ptr, qwT_ptr, qkv_ptr, S_LEN, QKV_N, HID);
    prep_fused<<<S_LEN + 1536, 256>>>(freqs, widx);
    attn_mma<<<dim3(S_LEN / 64, NH), 256, ATTN_SMEM>>>();
    split_planes<<<1024, 256>>>(o_w, wh_ptr, wl_ptr, HID * AO_N / 4);
    gemm_bf3<<<dim3(S_LEN / 128, HID / 128), 256, OGEMM_SMEM>>>(
        ah_ptr, al_ptr, wh_ptr, wl_ptr, out, S_LEN, HID, AO_N);
}